// round 2
// baseline (speedup 1.0000x reference)
#include <cuda_runtime.h>
#include <math.h>

// Shapes: A=16, NA=8, D_OBS=64, DZ=72, Bn=128, B*A=2048 rows.
// Output layout: value[128*16*16*8]=262144 | weight_z[32768] | weights_obsz[524288]

#define NTHREADS 256

// ---------------- intermediate storage (no allocs allowed) ----------------
__device__ float g_key_z  [2048*64];
__device__ float g_query_z[2048*64];
__device__ float g_w      [32768];      // sigmoid weights w[b,i,j]
__device__ float g_key_o  [2048*64];
__device__ float g_attn_src[2048*64];
__device__ float g_P      [2048*64];    // MLP_av(op)
__device__ float g_query_o[32768*64];
__device__ float g_S      [32768*64];   // MLP_av(obs_z)
__device__ float g_wo     [32768];      // softmax weights_o[b,i,j]

__device__ __forceinline__ float leaky(float x){ return x > 0.f ? x : 0.01f*x; }

// load weight matrix w[out=64][in_n] transposed into smem wt[c*65 + t]
__device__ __forceinline__ void load_wT(const float* __restrict__ w, int in_n, float* wt){
    for (int idx = threadIdx.x; idx < 64*in_n; idx += NTHREADS) {
        int t = idx / in_n, c = idx - t*in_n;
        wt[c*65 + t] = w[idx];
    }
}

// 64-row MLP tile: out = leaky(in @ W1^T + b1) @ W2^T + b2, all 64 hidden/out units.
// in_s: [64][CIN] (stride CIN), weights transposed stride 65. 256 threads.
template<int CIN>
__device__ void mlp_tile(const float* __restrict__ in_s,
                         const float* __restrict__ w1t, const float* __restrict__ b1,
                         const float* __restrict__ w2t, const float* __restrict__ b2,
                         float* hid, float* __restrict__ out_g, int row_base)
{
    int t  = threadIdx.x & 63;
    int rg = threadIdx.x >> 6;
    float bb1 = b1[t], bb2 = b2[t];
    #pragma unroll
    for (int r = rg; r < 64; r += 4) {
        float acc = bb1;
        const float* row = in_s + r*CIN;
        #pragma unroll
        for (int c = 0; c < CIN; c++) acc = fmaf(row[c], w1t[c*65 + t], acc);
        hid[r*64 + t] = leaky(acc);
    }
    __syncthreads();
    #pragma unroll
    for (int r = rg; r < 64; r += 4) {
        float acc = bb2;
        const float* row = hid + r*64;
        #pragma unroll
        for (int c = 0; c < 64; c++) acc = fmaf(row[c], w2t[c*65 + t], acc);
        out_g[(size_t)(row_base + r)*64 + t] = acc;
    }
    __syncthreads();
}

// ---------------- K1: key_z / query_z MLPs over obs (2048 rows) ----------------
__global__ void k1(const float* __restrict__ obs,
                   const float* kw1, const float* kb1, const float* kw2, const float* kb2,
                   const float* qw1, const float* qb1, const float* qw2, const float* qb2)
{
    extern __shared__ float sm[];
    float* w1a = sm;                 // 64*65
    float* w2a = w1a + 64*65;
    float* w1b = w2a + 64*65;
    float* w2b = w1b + 64*65;
    float* in_s = w2b + 64*65;       // 64*64
    float* hid  = in_s + 64*64;      // 64*64
    load_wT(kw1, 64, w1a); load_wT(kw2, 64, w2a);
    load_wT(qw1, 64, w1b); load_wT(qw2, 64, w2b);
    int row_base = blockIdx.x * 64;
    for (int idx = threadIdx.x; idx < 64*64; idx += NTHREADS)
        in_s[idx] = obs[(size_t)row_base*64 + idx];
    __syncthreads();
    mlp_tile<64>(in_s, w1a, kb1, w2a, kb2, hid, g_key_z,   row_base);
    mlp_tile<64>(in_s, w1b, qb1, w2b, qb2, hid, g_query_z, row_base);
}

// ---------------- K2: score -> sigmoid w, write weight_z output ----------------
__global__ void k2(float* __restrict__ out_wz)
{
    __shared__ float q_s[16*65], k_s[16*65];
    int b = blockIdx.x;
    for (int idx = threadIdx.x; idx < 1024; idx += NTHREADS) {
        int r = idx >> 6, c = idx & 63;
        q_s[r*65 + c] = g_query_z[(b*16 + r)*64 + c];
        k_s[r*65 + c] = g_key_z  [(b*16 + r)*64 + c];
    }
    __syncthreads();
    int i = threadIdx.x >> 4, j = threadIdx.x & 15;
    float acc = 0.f;
    #pragma unroll
    for (int d = 0; d < 64; d++) acc = fmaf(q_s[i*65 + d], k_s[j*65 + d], acc);
    float w = 1.f / (1.f + expf(-acc * 0.125f));   // d_k_w = 8
    g_w  [b*256 + threadIdx.x] = w;
    out_wz[b*256 + threadIdx.x] = w;
}

// ---------------- K3: key_o, attn_src (on src rows) and P (on op rows) ----------------
__global__ void k3(const float* __restrict__ obs, const float* __restrict__ pol,
                   const float* __restrict__ act,
                   const float* ko1, const float* ko1b, const float* ko2, const float* ko2b,
                   const float* av1, const float* av1b, const float* av2, const float* av2b)
{
    extern __shared__ float sm[];
    float* w1k  = sm;                 // 72*65
    float* w2k  = w1k + 72*65;        // 64*65
    float* w1a  = w2k + 64*65;        // 72*65
    float* w2a  = w1a + 72*65;        // 64*65
    float* src_s = w2a + 64*65;       // 64*72
    float* op_s  = src_s + 64*72;     // 64*72
    float* hid   = op_s + 64*72;      // 64*64
    load_wT(ko1, 72, w1k); load_wT(ko2, 64, w2k);
    load_wT(av1, 72, w1a); load_wT(av2, 64, w2a);
    int row_base = blockIdx.x * 64;   // row index over (b,i)
    for (int idx = threadIdx.x; idx < 64*72; idx += NTHREADS) {
        int r = idx / 72, c = idx - r*72;
        int g = row_base + r;
        float vs, vo;
        if (c < 64) { float o = obs[(size_t)g*64 + c]; vs = o; vo = o; }
        else {
            int n = c - 64;
            float wv = g_w[g*16 + (g & 15)];          // w[b,i,i]
            float a = act[g*8 + n], p = pol[g*8 + n];
            vs = wv*a + (1.f - wv)*p;                 // z[b,i,i]
            vo = p;                                   // op = [obs, pi]
        }
        src_s[idx] = vs; op_s[idx] = vo;
    }
    __syncthreads();
    mlp_tile<72>(src_s, w1k, ko1b, w2k, ko2b, hid, g_key_o,    row_base);
    mlp_tile<72>(src_s, w1a, av1b, w2a, av2b, hid, g_attn_src, row_base);
    mlp_tile<72>(op_s,  w1a, av1b, w2a, av2b, hid, g_P,        row_base);
}

// ---------------- K4: query_o and S MLPs on obs_z (32768 rows) ----------------
__global__ void k4(const float* __restrict__ obs, const float* __restrict__ pol,
                   const float* __restrict__ act,
                   const float* qo1, const float* qo1b, const float* qo2, const float* qo2b,
                   const float* av1, const float* av1b, const float* av2, const float* av2b)
{
    extern __shared__ float sm[];
    float* w1q = sm;                  // 72*65
    float* w2q = w1q + 72*65;         // 64*65
    float* w1a = w2q + 64*65;         // 72*65
    float* w2a = w1a + 72*65;         // 64*65
    float* in_s = w2a + 64*65;        // 64*72
    float* hid  = in_s + 64*72;       // 64*64
    load_wT(qo1, 72, w1q); load_wT(qo2, 64, w2q);
    load_wT(av1, 72, w1a); load_wT(av2, 64, w2a);
    int row_base = blockIdx.x * 64;   // row over (b,i,j): g = b*256 + i*16 + j
    for (int idx = threadIdx.x; idx < 64*72; idx += NTHREADS) {
        int r = idx / 72, c = idx - r*72;
        int g = row_base + r;
        int bj = ((g >> 8) << 4) | (g & 15);          // b*16 + j
        float v;
        if (c < 64) v = obs[(size_t)bj*64 + c];
        else {
            int n = c - 64;
            float wv = g_w[g];
            v = wv*act[bj*8 + n] + (1.f - wv)*pol[bj*8 + n];
        }
        in_s[idx] = v;
    }
    __syncthreads();
    mlp_tile<72>(in_s, w1q, qo1b, w2q, qo2b, hid, g_query_o, row_base);
    mlp_tile<72>(in_s, w1a, av1b, w2a, av2b, hid, g_S,       row_base);
}

// ---------------- K5: score_o -> exp(clip) -> softmax over j ----------------
__global__ void k5()
{
    extern __shared__ float sm[];
    float* k_s = sm;            // 16*65
    float* q_s = sm + 16*65;    // 256*65
    int b = blockIdx.x;
    for (int idx = threadIdx.x; idx < 1024; idx += NTHREADS) {
        int r = idx >> 6, c = idx & 63;
        k_s[r*65 + c] = g_key_o[(b*16 + r)*64 + c];
    }
    for (int idx = threadIdx.x; idx < 16384; idx += NTHREADS) {
        int r = idx >> 6, c = idx & 63;
        q_s[r*65 + c] = g_query_o[(size_t)(b*256 + r)*64 + c];
    }
    __syncthreads();
    int i = threadIdx.x >> 4;                        // agent i
    float acc = 0.f;
    int pair = threadIdx.x;
    #pragma unroll
    for (int d = 0; d < 64; d++) acc = fmaf(k_s[i*65 + d], q_s[pair*65 + d], acc);
    float sc = fminf(fmaxf(acc * 0.125f, -5.f), 5.f);  // clip(score/8)
    float t = expf(sc);
    // stable softmax over j (16-lane groups, xor shuffles stay in group)
    float mx = t;
    #pragma unroll
    for (int m = 1; m < 16; m <<= 1) mx = fmaxf(mx, __shfl_xor_sync(0xffffffffu, mx, m));
    float e = expf(t - mx), s = e;
    #pragma unroll
    for (int m = 1; m < 16; m <<= 1) s += __shfl_xor_sync(0xffffffffu, s, m);
    g_wo[b*256 + threadIdx.x] = e / s;
}

// ---------------- K6: mixed + value head ----------------
__global__ void k6(const float* __restrict__ fv1, const float* __restrict__ fv1b,
                   const float* __restrict__ fv2, const float* __restrict__ fv2b,
                   float* __restrict__ out_val)
{
    extern __shared__ float sm[];
    float* S_s   = sm;               // 256*65 = 16640
    float* P_s   = S_s + 16640;      // 16*65  = 1040
    float* as_s  = P_s + 1040;       // 16*65  = 1040
    float* fv1_s = as_s + 1040;      // 64*129 = 8256
    float* fv2_s = fv1_s + 8256;     // 512
    float* U_s   = fv2_s + 512;      // 16*64  = 1024
    float* wo_s  = U_s + 1024;       // 256
    int b = blockIdx.x;
    for (int idx = threadIdx.x; idx < 16384; idx += NTHREADS) {
        int r = idx >> 6, c = idx & 63;
        S_s[r*65 + c] = g_S[(size_t)(b*256 + r)*64 + c];
    }
    for (int idx = threadIdx.x; idx < 1024; idx += NTHREADS) {
        int r = idx >> 6, c = idx & 63;
        P_s [r*65 + c] = g_P       [(b*16 + r)*64 + c];
        as_s[r*65 + c] = g_attn_src[(b*16 + r)*64 + c];
    }
    for (int idx = threadIdx.x; idx < 8192; idx += NTHREADS) {
        int t = idx >> 7, c = idx & 127;
        fv1_s[t*129 + c] = fv1[idx];
    }
    for (int idx = threadIdx.x; idx < 512; idx += NTHREADS) fv2_s[idx] = fv2[idx];
    wo_s[threadIdx.x] = g_wo[b*256 + threadIdx.x];
    __syncthreads();
    // U[a][t] = fv1b[t] + fv1[t, 0:64] . attn_src[a]
    // NOTE: src_rep[b,i,j] = attn_src[b, j]  (broadcast inserts axis at i), so
    // the value head consumes U indexed by j, not i.
    for (int idx = threadIdx.x; idx < 1024; idx += NTHREADS) {
        int a = idx >> 6, t = idx & 63;
        float acc = fv1b[t];
        #pragma unroll
        for (int c = 0; c < 64; c++) acc = fmaf(fv1_s[t*129 + c], as_s[a*65 + c], acc);
        U_s[a*64 + t] = acc;
    }
    __syncthreads();

    int i = threadIdx.x >> 4, j = threadIdx.x & 15;
    float accd[64];
    float wjj = wo_s[j*16 + j];
    {
        const float* Sr = &S_s[(i*16 + j)*65];
        const float* Pr = &P_s[j*65];
        #pragma unroll
        for (int d = 0; d < 64; d++) accd[d] = (Pr[d] - Sr[d]) * wjj;  // diag correction
    }
    for (int k = 0; k < 16; k++) {
        float wk = wo_s[j*16 + k];
        const float* Sr = &S_s[(i*16 + k)*65];
        #pragma unroll
        for (int d = 0; d < 64; d++) accd[d] = fmaf(wk, Sr[d], accd[d]);
    }
    #pragma unroll
    for (int d = 0; d < 64; d++) accd[d] *= 0.0625f;   // mean over A=16

    float vout[8];
    #pragma unroll
    for (int o = 0; o < 8; o++) vout[o] = fv2b[o];
    for (int t = 0; t < 64; t++) {
        float h = U_s[j*64 + t];                       // <-- fixed: index by j
        const float* f = &fv1_s[t*129 + 64];
        #pragma unroll
        for (int c = 0; c < 64; c++) h = fmaf(f[c], accd[c], h);
        h = leaky(h);
        #pragma unroll
        for (int o = 0; o < 8; o++) vout[o] = fmaf(fv2_s[o*64 + t], h, vout[o]);
    }
    float* dst = out_val + (size_t)(b*256 + threadIdx.x)*8;
    #pragma unroll
    for (int o = 0; o < 8; o++) dst[o] = vout[o];
}

// ---------------- K7: weights_obsz broadcast ----------------
__global__ void k7(float* __restrict__ out_obsz)
{
    int idx = blockIdx.x * blockDim.x + threadIdx.x;      // (b,i,j,k) flat, 524288
    out_obsz[idx] = g_wo[((idx >> 12) << 8) | (idx & 255)];
}

// ---------------- launcher ----------------
extern "C" void kernel_launch(void* const* d_in, const int* in_sizes, int n_in,
                              void* d_out, int out_size)
{
    const float* obs  = (const float*)d_in[0];
    const float* pol  = (const float*)d_in[1];
    const float* act  = (const float*)d_in[2];
    const float* kw1  = (const float*)d_in[3];  const float* kw1b = (const float*)d_in[4];
    const float* kw2  = (const float*)d_in[5];  const float* kw2b = (const float*)d_in[6];
    const float* qw1  = (const float*)d_in[7];  const float* qw1b = (const float*)d_in[8];
    const float* qw2  = (const float*)d_in[9];  const float* qw2b = (const float*)d_in[10];
    const float* ko1  = (const float*)d_in[11]; const float* ko1b = (const float*)d_in[12];
    const float* ko2  = (const float*)d_in[13]; const float* ko2b = (const float*)d_in[14];
    const float* qo1  = (const float*)d_in[15]; const float* qo1b = (const float*)d_in[16];
    const float* qo2  = (const float*)d_in[17]; const float* qo2b = (const float*)d_in[18];
    const float* av1  = (const float*)d_in[19]; const float* av1b = (const float*)d_in[20];
    const float* av2  = (const float*)d_in[21]; const float* av2b = (const float*)d_in[22];
    const float* fv1  = (const float*)d_in[23]; const float* fv1b = (const float*)d_in[24];
    const float* fv2  = (const float*)d_in[25]; const float* fv2b = (const float*)d_in[26];

    float* out      = (float*)d_out;
    float* out_val  = out;             // 262144
    float* out_wz   = out + 262144;    // 32768
    float* out_obsz = out + 294912;    // 524288

    const int SM1 = (4*64*65 + 2*64*64) * 4;                              // 99328
    const int SM3 = (2*72*65 + 2*64*65 + 2*64*72 + 64*64) * 4;            // 123968
    const int SM4 = (2*72*65 + 2*64*65 + 64*72 + 64*64) * 4;              // 105536
    const int SM5 = (16*65 + 256*65) * 4;                                 // 70720
    const int SM6 = (16640 + 1040 + 1040 + 8256 + 512 + 1024 + 256) * 4;  // 115072

    cudaFuncSetAttribute(k1, cudaFuncAttributeMaxDynamicSharedMemorySize, SM1);
    cudaFuncSetAttribute(k3, cudaFuncAttributeMaxDynamicSharedMemorySize, SM3);
    cudaFuncSetAttribute(k4, cudaFuncAttributeMaxDynamicSharedMemorySize, SM4);
    cudaFuncSetAttribute(k5, cudaFuncAttributeMaxDynamicSharedMemorySize, SM5);
    cudaFuncSetAttribute(k6, cudaFuncAttributeMaxDynamicSharedMemorySize, SM6);

    k1<<<32,  NTHREADS, SM1>>>(obs, kw1, kw1b, kw2, kw2b, qw1, qw1b, qw2, qw2b);
    k2<<<128, NTHREADS>>>(out_wz);
    k3<<<32,  NTHREADS, SM3>>>(obs, pol, act, ko1, ko1b, ko2, ko2b, av1, av1b, av2, av2b);
    k4<<<512, NTHREADS, SM4>>>(obs, pol, act, qo1, qo1b, qo2, qo2b, av1, av1b, av2, av2b);
    k5<<<128, NTHREADS, SM5>>>();
    k6<<<128, NTHREADS, SM6>>>(fv1, fv1b, fv2, fv2b, out_val);
    k7<<<2048, NTHREADS>>>(out_obsz);
}

// round 4
// speedup vs baseline: 1.2217x; 1.2217x over previous
#include <cuda_runtime.h>
#include <math.h>

// A=16, NA=8, D_OBS=64, DZ=72, Bn=128. 2048 (b,agent) rows, 32768 (b,i,j) rows.
// Output: value[262144] | weight_z[32768] | weights_obsz[524288]

#define NTHREADS 256

// ---------------- intermediates ----------------
__device__ float g_key_z  [2048*64];
__device__ float g_query_z[2048*64];
__device__ float g_w      [32768];
__device__ float g_key_o  [2048*64];
__device__ float g_attn_src[2048*64];
__device__ float g_P      [2048*64];
__device__ float g_u_qo   [2048*64];
__device__ float g_v_qo   [2048*64];
__device__ float g_u_av   [2048*64];
__device__ float g_v_av   [2048*64];
__device__ float g_kq     [2048*64];
__device__ float g_kb     [2048];
__device__ float g_U      [2048*64];
__device__ float g_FmP    [2048*64];
__device__ float g_wo     [32768];
__device__ float g_G      [32768*64];
__device__ float g_Ct     [64*65];
__device__ float g_fb     [64];

__device__ __forceinline__ float leaky(float x){ return x > 0.f ? x : 0.01f*x; }

// w[64 out][in_n] -> wt[c*65 + t] (transposed, padded)
__device__ __forceinline__ void load_wT(const float* __restrict__ w, int in_n, float* wt){
    for (int idx = threadIdx.x; idx < 64*in_n; idx += NTHREADS) {
        int t = idx / in_n, c = idx - t*in_n;
        wt[c*65 + t] = w[idx];
    }
}

// out[r][t] = (LK?leaky:id)(bias[t] + sum_c in_s[r*LDIN+c] * wT[c*65+t]),
// 64 rows x 64 outs, 256 threads: thread owns t, 16 rows in register accumulators.
// in_s rows 16B-aligned, LDIN % 4 == 0. Input loads are warp-broadcast float4.
template<int CIN, int LDIN, bool LK>
__device__ __forceinline__ void gemm_rows(const float* __restrict__ in_s,
                                          const float* __restrict__ wT,
                                          const float* __restrict__ bias,
                                          float* __restrict__ out, int ldout)
{
    int t  = threadIdx.x & 63;
    int rg = threadIdx.x >> 6;
    float b = bias ? bias[t] : 0.f;
    float acc[16];
    #pragma unroll
    for (int k = 0; k < 16; k++) acc[k] = b;
    for (int c4 = 0; c4 < CIN/4; c4++) {
        float w0 = wT[(c4*4+0)*65 + t];
        float w1 = wT[(c4*4+1)*65 + t];
        float w2 = wT[(c4*4+2)*65 + t];
        float w3 = wT[(c4*4+3)*65 + t];
        #pragma unroll
        for (int k = 0; k < 16; k++) {
            float4 v = *reinterpret_cast<const float4*>(&in_s[(rg*16+k)*LDIN + c4*4]);
            acc[k] = fmaf(v.x, w0, fmaf(v.y, w1, fmaf(v.z, w2, fmaf(v.w, w3, acc[k]))));
        }
    }
    #pragma unroll
    for (int k = 0; k < 16; k++)
        out[(rg*16+k)*ldout + t] = LK ? leaky(acc[k]) : acc[k];
}

// ---------------- KA: key_z / query_z (2048 rows) ----------------
__global__ void kA(const float* __restrict__ obs,
                   const float* kw1, const float* kb1, const float* kw2, const float* kb2,
                   const float* qw1, const float* qb1, const float* qw2, const float* qb2)
{
    extern __shared__ float sm[];
    float* w1k = sm;            // 4160
    float* w2k = sm + 4160;
    float* w1q = sm + 8320;
    float* w2q = sm + 12480;
    float* in_s = sm + 16640;   // 64*64
    float* hid  = sm + 20736;   // 64*64
    load_wT(kw1, 64, w1k); load_wT(kw2, 64, w2k);
    load_wT(qw1, 64, w1q); load_wT(qw2, 64, w2q);
    int rb = blockIdx.x * 64;
    for (int idx = threadIdx.x; idx < 4096; idx += NTHREADS) in_s[idx] = obs[(size_t)rb*64 + idx];
    __syncthreads();
    gemm_rows<64,64,true >(in_s, w1k, kb1, hid, 64);
    __syncthreads();
    gemm_rows<64,64,false>(hid,  w2k, kb2, g_key_z + (size_t)rb*64, 64);
    __syncthreads();
    gemm_rows<64,64,true >(in_s, w1q, qb1, hid, 64);
    __syncthreads();
    gemm_rows<64,64,false>(hid,  w2q, qb2, g_query_z + (size_t)rb*64, 64);
}

// ---------------- KB: sigmoid attention weights w ----------------
__global__ void kB(float* __restrict__ out_wz)
{
    __shared__ float q_s[16*65], k_s[16*65];
    int b = blockIdx.x;
    for (int idx = threadIdx.x; idx < 1024; idx += NTHREADS) {
        int r = idx >> 6, c = idx & 63;
        q_s[r*65 + c] = g_query_z[b*1024 + idx];
        k_s[r*65 + c] = g_key_z  [b*1024 + idx];
    }
    __syncthreads();
    int i = threadIdx.x >> 4, j = threadIdx.x & 15;
    float acc = 0.f;
    #pragma unroll
    for (int d = 0; d < 64; d++) acc = fmaf(q_s[i*65 + d], k_s[j*65 + d], acc);
    float w = 1.f / (1.f + expf(-acc * 0.125f));
    g_w  [b*256 + threadIdx.x] = w;
    out_wz[b*256 + threadIdx.x] = w;
}

// ---------------- KC: key_o, attn_src (src rows), P (op rows) ----------------
__global__ void kC(const float* __restrict__ obs, const float* __restrict__ pol,
                   const float* __restrict__ act,
                   const float* ko1, const float* ko1b, const float* ko2, const float* ko2b,
                   const float* av1, const float* av1b, const float* av2, const float* av2b)
{
    extern __shared__ float sm[];
    float* w1k  = sm;            // 4680
    float* w2k  = sm + 4680;     // 4160
    float* w1a  = sm + 8840;     // 4680
    float* w2a  = sm + 13520;    // 4160
    float* src_s = sm + 17680;   // 64*72
    float* op_s  = sm + 22288;   // 64*72
    float* hid   = sm + 26896;   // 64*64
    load_wT(ko1, 72, w1k); load_wT(ko2, 64, w2k);
    load_wT(av1, 72, w1a); load_wT(av2, 64, w2a);
    int rb = blockIdx.x * 64;
    for (int idx = threadIdx.x; idx < 64*72; idx += NTHREADS) {
        int r = idx / 72, c = idx - r*72;
        int g = rb + r;
        float vs, vo;
        if (c < 64) { float o = obs[(size_t)g*64 + c]; vs = o; vo = o; }
        else {
            int n = c - 64;
            float wv = g_w[g*16 + (g & 15)];
            float a = act[g*8 + n], p = pol[g*8 + n];
            vs = fmaf(wv, a - p, p);
            vo = p;
        }
        src_s[idx] = vs; op_s[idx] = vo;
    }
    __syncthreads();
    gemm_rows<72,72,true >(src_s, w1k, ko1b, hid, 64);
    __syncthreads();
    gemm_rows<64,64,false>(hid,   w2k, ko2b, g_key_o + (size_t)rb*64, 64);
    __syncthreads();
    gemm_rows<72,72,true >(src_s, w1a, av1b, hid, 64);
    __syncthreads();
    gemm_rows<64,64,false>(hid,   w2a, av2b, g_attn_src + (size_t)rb*64, 64);
    __syncthreads();
    gemm_rows<72,72,true >(op_s,  w1a, av1b, hid, 64);
    __syncthreads();
    gemm_rows<64,64,false>(hid,   w2a, av2b, g_P + (size_t)rb*64, 64);
}

// ---------------- KD1: per-(b,j) layer-1 decompositions u/v for qo & av ----------------
__global__ void kD1(const float* __restrict__ obs, const float* __restrict__ pol,
                    const float* __restrict__ act,
                    const float* qo1, const float* qo1b,
                    const float* av1, const float* av1b)
{
    extern __shared__ float sm[];
    float* w1q = sm;            // 4680
    float* w1a = sm + 4680;     // 4680
    float* ip  = sm + 9360;     // 64*72
    float* dl  = sm + 13968;    // 64*8
    load_wT(qo1, 72, w1q); load_wT(av1, 72, w1a);
    int rb = blockIdx.x * 64;
    for (int idx = threadIdx.x; idx < 64*72; idx += NTHREADS) {
        int r = idx / 72, c = idx - r*72;
        ip[idx] = (c < 64) ? obs[(size_t)(rb+r)*64 + c] : pol[(rb+r)*8 + c - 64];
    }
    for (int idx = threadIdx.x; idx < 512; idx += NTHREADS) {
        int r = idx >> 3, c = idx & 7;
        dl[idx] = act[(rb+r)*8 + c] - pol[(rb+r)*8 + c];
    }
    __syncthreads();
    gemm_rows<72,72,false>(ip, w1q,          qo1b,    g_u_qo + (size_t)rb*64, 64);
    gemm_rows< 8, 8,false>(dl, w1q + 64*65,  nullptr, g_v_qo + (size_t)rb*64, 64);
    gemm_rows<72,72,false>(ip, w1a,          av1b,    g_u_av + (size_t)rb*64, 64);
    gemm_rows< 8, 8,false>(dl, w1a + 64*65,  nullptr, g_v_av + (size_t)rb*64, 64);
}

// ---------------- KD2: kq/kb (fold qo layer-2 into key), U, FmP ----------------
__global__ void kD2(const float* __restrict__ qo2, const float* __restrict__ qo2b,
                    const float* __restrict__ fv1, const float* __restrict__ fv1b)
{
    extern __shared__ float sm[];
    float* qo2p = sm;            // 4160 (NOT transposed: wT[c*65+t]=qo2[c][t] -> W2^T x)
    float* f1a  = sm + 4160;     // 4160  fv1[:, :64]^T
    float* fmt  = sm + 8320;     // 4160  fv1[:, 64:]^T
    float* ko_s = sm + 12480;    // 4096
    float* as_s = sm + 16576;    // 4096
    float* P_s  = sm + 20672;    // 4096
    float* b2_s = sm + 24768;    // 64
    for (int idx = threadIdx.x; idx < 4096; idx += NTHREADS) {
        int c = idx >> 6, t = idx & 63;
        qo2p[c*65 + t] = qo2[idx];
        f1a [t*65 + c] = fv1[c*128 + t];       // wt[c'*65+t'] = fv1[t'][c'], c'=t, t'=c
        fmt [t*65 + c] = fv1[c*128 + 64 + t];
    }
    if (threadIdx.x < 64) b2_s[threadIdx.x] = qo2b[threadIdx.x];
    int rb = blockIdx.x * 64;
    for (int idx = threadIdx.x; idx < 4096; idx += NTHREADS) {
        ko_s[idx] = g_key_o   [(size_t)rb*64 + idx];
        as_s[idx] = g_attn_src[(size_t)rb*64 + idx];
        P_s [idx] = g_P       [(size_t)rb*64 + idx];
    }
    __syncthreads();
    if (threadIdx.x < 64) {
        int r = threadIdx.x;
        float s = 0.f;
        for (int c = 0; c < 64; c++) {
            int cc = (c + r) & 63;                 // rotate to avoid bank conflicts
            s = fmaf(ko_s[r*64 + cc], b2_s[cc], s);
        }
        g_kb[rb + r] = s;
    }
    gemm_rows<64,64,false>(ko_s, qo2p, nullptr, g_kq  + (size_t)rb*64, 64);
    gemm_rows<64,64,false>(as_s, f1a,  fv1b,    g_U   + (size_t)rb*64, 64);
    gemm_rows<64,64,false>(P_s,  fmt,  nullptr, g_FmP + (size_t)rb*64, 64);
}

// ---------------- KE: score_o (never materializing query_o) + softmax ----------------
__global__ void kE()
{
    __shared__ float kq_s[16*65], uq_s[16*65], vq_s[16*65], kb_s[16], w_s[256];
    int b = blockIdx.x;
    for (int idx = threadIdx.x; idx < 1024; idx += NTHREADS) {
        int r = idx >> 6, c = idx & 63;
        kq_s[r*65 + c] = g_kq  [b*1024 + idx];
        uq_s[r*65 + c] = g_u_qo[b*1024 + idx];
        vq_s[r*65 + c] = g_v_qo[b*1024 + idx];
    }
    if (threadIdx.x < 16) kb_s[threadIdx.x] = g_kb[b*16 + threadIdx.x];
    w_s[threadIdx.x] = g_w[b*256 + threadIdx.x];
    __syncthreads();
    int i = threadIdx.x >> 4, j = threadIdx.x & 15;
    float wv = w_s[threadIdx.x];
    float acc = kb_s[i];
    #pragma unroll
    for (int d = 0; d < 64; d++) {
        float h = leaky(fmaf(wv, vq_s[j*65 + d], uq_s[j*65 + d]));
        acc = fmaf(kq_s[i*65 + d], h, acc);
    }
    float sc = fminf(fmaxf(acc * 0.125f, -5.f), 5.f);
    float t = expf(sc);
    float mx = t;
    #pragma unroll
    for (int m = 1; m < 16; m <<= 1) mx = fmaxf(mx, __shfl_xor_sync(0xffffffffu, mx, m));
    float e = expf(t - mx), s = e;
    #pragma unroll
    for (int m = 1; m < 16; m <<= 1) s += __shfl_xor_sync(0xffffffffu, s, m);
    g_wo[b*256 + threadIdx.x] = e / s;
}

// ---------------- KF0: C^T = (Fm @ av2_w)^T and fb = Fm @ av2_b ----------------
__global__ void kF0(const float* __restrict__ fv1, const float* __restrict__ av2w,
                    const float* __restrict__ av2b)
{
    __shared__ float fm[64*64], w2t[64*65], b2[64];
    for (int idx = threadIdx.x; idx < 4096; idx += NTHREADS) {
        int t = idx >> 6, c = idx & 63;
        fm[idx] = fv1[t*128 + 64 + c];
        w2t[(idx & 63)*65 + (idx >> 6)] = av2w[idx];   // w2t[e*65+c] = av2w[c][e]
    }
    if (threadIdx.x < 64) b2[threadIdx.x] = av2b[threadIdx.x];
    __syncthreads();
    for (int idx = threadIdx.x; idx < 4096; idx += NTHREADS) {
        int t = idx & 63, e = idx >> 6;
        float s = 0.f;
        for (int c = 0; c < 64; c++) {
            int cc = (c + t) & 63;
            s = fmaf(fm[t*64 + cc], w2t[e*65 + cc], s);
        }
        g_Ct[e*65 + t] = s;
    }
    if (threadIdx.x < 64) {
        int t = threadIdx.x;
        float s = 0.f;
        for (int c = 0; c < 64; c++) {
            int cc = (c + t) & 63;
            s = fmaf(fm[t*64 + cc], b2[cc], s);
        }
        g_fb[t] = s;
    }
}

// ---------------- KF: L = leaky(u + w*v); G = C @ L  (the one big GEMM) ----------------
__global__ void kF()
{
    extern __shared__ float sm[];
    float* Ct_s = sm;            // 4160
    float* L_s  = sm + 4160;     // 4096
    float* u_s  = sm + 8256;     // 1024
    float* v_s  = sm + 9280;     // 1024
    float* w_s  = sm + 10304;    // 64
    int rb = blockIdx.x * 64;
    int b  = rb >> 8;
    for (int idx = threadIdx.x; idx < 4160; idx += NTHREADS) Ct_s[idx] = g_Ct[idx];
    for (int idx = threadIdx.x; idx < 1024; idx += NTHREADS) {
        u_s[idx] = g_u_av[b*1024 + idx];
        v_s[idx] = g_v_av[b*1024 + idx];
    }
    if (threadIdx.x < 64) w_s[threadIdx.x] = g_w[rb + threadIdx.x];
    __syncthreads();
    for (int idx = threadIdx.x; idx < 4096; idx += NTHREADS) {
        int r = idx >> 6, t = idx & 63;
        int j = r & 15;
        L_s[idx] = leaky(fmaf(w_s[r], v_s[j*64 + t], u_s[j*64 + t]));
    }
    __syncthreads();
    gemm_rows<64,64,false>(L_s, Ct_s, nullptr, g_G + (size_t)rb*64, 64);
}

// ---------------- KG: value head (mix G with wo, fv1/fv2 folded) ----------------
__global__ void kG(const float* __restrict__ fv2, const float* __restrict__ fv2b,
                   float* __restrict__ out_val)
{
    extern __shared__ float sm[];
    float* G_s   = sm;             // 256*65 = 16640
    float* U_s   = sm + 16640;     // 16*65
    float* Fp_s  = sm + 17680;     // 16*65
    float* fb_s  = sm + 18720;     // 64
    float* fv2_s = sm + 18784;     // 512
    float* wo_s  = sm + 19296;     // 256
    float* b2v   = sm + 19552;     // 8
    int b = blockIdx.x;
    for (int idx = threadIdx.x; idx < 16384; idx += NTHREADS) {
        int r = idx >> 6, c = idx & 63;
        G_s[r*65 + c] = g_G[(size_t)b*16384 + idx];
    }
    for (int idx = threadIdx.x; idx < 1024; idx += NTHREADS) {
        int r = idx >> 6, c = idx & 63;
        U_s [r*65 + c] = g_U  [b*1024 + idx];
        Fp_s[r*65 + c] = g_FmP[b*1024 + idx];
    }
    if (threadIdx.x < 64) fb_s[threadIdx.x] = g_fb[threadIdx.x];
    for (int idx = threadIdx.x; idx < 512; idx += NTHREADS) fv2_s[idx] = fv2[idx];
    wo_s[threadIdx.x] = g_wo[b*256 + threadIdx.x];
    if (threadIdx.x < 8) b2v[threadIdx.x] = fv2b[threadIdx.x];
    __syncthreads();
    int i = threadIdx.x >> 4, j = threadIdx.x & 15;
    float wo_r[16];
    #pragma unroll
    for (int k = 0; k < 16; k++) wo_r[k] = wo_s[j*16 + k];
    float wjj = wo_r[j];
    float vout[8];
    #pragma unroll
    for (int o = 0; o < 8; o++) vout[o] = b2v[o];
    for (int t = 0; t < 64; t++) {
        float m = 0.f;
        #pragma unroll
        for (int k = 0; k < 16; k++) m = fmaf(wo_r[k], G_s[(i*16 + k)*65 + t], m);
        float gij = G_s[(i*16 + j)*65 + t];
        float fbt = fb_s[t];
        float h = U_s[j*65 + t] + 0.0625f * (m + fbt + wjj * (Fp_s[j*65 + t] - gij - fbt));
        float ht = leaky(h);
        #pragma unroll
        for (int o = 0; o < 8; o++) vout[o] = fmaf(fv2_s[o*64 + t], ht, vout[o]);
    }
    float4* dst = reinterpret_cast<float4*>(out_val + (size_t)(b*256 + threadIdx.x)*8);
    dst[0] = make_float4(vout[0], vout[1], vout[2], vout[3]);
    dst[1] = make_float4(vout[4], vout[5], vout[6], vout[7]);
}

// ---------------- KH: weights_obsz broadcast (vectorized) ----------------
__global__ void kH(float4* __restrict__ out4)
{
    int q = blockIdx.x * NTHREADS + threadIdx.x;   // < 131072
    int idx = q << 2;
    const float4* wo4 = reinterpret_cast<const float4*>(g_wo);
    out4[q] = wo4[(((idx >> 12) << 8) | (idx & 255)) >> 2];
}

// ---------------- launcher ----------------
extern "C" void kernel_launch(void* const* d_in, const int* in_sizes, int n_in,
                              void* d_out, int out_size)
{
    const float* obs  = (const float*)d_in[0];
    const float* pol  = (const float*)d_in[1];
    const float* act  = (const float*)d_in[2];
    const float* kw1  = (const float*)d_in[3];  const float* kw1b = (const float*)d_in[4];
    const float* kw2  = (const float*)d_in[5];  const float* kw2b = (const float*)d_in[6];
    const float* qw1  = (const float*)d_in[7];  const float* qw1b = (const float*)d_in[8];
    const float* qw2  = (const float*)d_in[9];  const float* qw2b = (const float*)d_in[10];
    const float* ko1  = (const float*)d_in[11]; const float* ko1b = (const float*)d_in[12];
    const float* ko2  = (const float*)d_in[13]; const float* ko2b = (const float*)d_in[14];
    const float* qo1  = (const float*)d_in[15]; const float* qo1b = (const float*)d_in[16];
    const float* qo2  = (const float*)d_in[17]; const float* qo2b = (const float*)d_in[18];
    const float* av1  = (const float*)d_in[19]; const float* av1b = (const float*)d_in[20];
    const float* av2  = (const float*)d_in[21]; const float* av2b = (const float*)d_in[22];
    const float* fv1  = (const float*)d_in[23]; const float* fv1b = (const float*)d_in[24];
    const float* fv2  = (const float*)d_in[25]; const float* fv2b = (const float*)d_in[26];

    float* out      = (float*)d_out;
    float* out_val  = out;
    float* out_wz   = out + 262144;
    float* out_obsz = out + 294912;

    const int SMA  = 24832 * 4;   // kA
    const int SMC  = 30992 * 4;   // kC
    const int SMD1 = 14480 * 4;
    const int SMD2 = 24832 * 4;
    const int SMF  = 10368 * 4;
    const int SMG  = 19560 * 4;

    cudaFuncSetAttribute(kA,  cudaFuncAttributeMaxDynamicSharedMemorySize, SMA);
    cudaFuncSetAttribute(kC,  cudaFuncAttributeMaxDynamicSharedMemorySize, SMC);
    cudaFuncSetAttribute(kD1, cudaFuncAttributeMaxDynamicSharedMemorySize, SMD1);
    cudaFuncSetAttribute(kD2, cudaFuncAttributeMaxDynamicSharedMemorySize, SMD2);
    cudaFuncSetAttribute(kF,  cudaFuncAttributeMaxDynamicSharedMemorySize, SMF);
    cudaFuncSetAttribute(kG,  cudaFuncAttributeMaxDynamicSharedMemorySize, SMG);

    kA <<<32,  NTHREADS, SMA >>>(obs, kw1, kw1b, kw2, kw2b, qw1, qw1b, qw2, qw2b);
    kB <<<128, NTHREADS      >>>(out_wz);
    kC <<<32,  NTHREADS, SMC >>>(obs, pol, act, ko1, ko1b, ko2, ko2b, av1, av1b, av2, av2b);
    kD1<<<32,  NTHREADS, SMD1>>>(obs, pol, act, qo1, qo1b, av1, av1b);
    kD2<<<32,  NTHREADS, SMD2>>>(qo2, qo2b, fv1, fv1b);
    kE <<<128, NTHREADS      >>>();
    kF0<<<1,   NTHREADS      >>>(fv1, av2, av2b);
    kF <<<512, NTHREADS, SMF >>>();
    kG <<<128, NTHREADS, SMG >>>(fv2, fv2b, out_val);
    kH <<<512, NTHREADS      >>>(reinterpret_cast<float4*>(out_obsz));
}

// round 5
// speedup vs baseline: 1.9563x; 1.6012x over previous
#include <cuda_runtime.h>
#include <math.h>

// A=16, NA=8, D_OBS=64, DZ=72, Bn=128. 2048 (b,agent) rows, 32768 (b,i,j) rows.
// Output: value[262144] | weight_z[32768] | weights_obsz[524288]

#define NTHREADS 256

// ---------------- intermediates ----------------
__device__ float g_key_z  [2048*64];
__device__ float g_query_z[2048*64];
__device__ float g_w      [32768];
__device__ float g_key_o  [2048*64];
__device__ float g_attn_src[2048*64];
__device__ float g_P      [2048*64];
__device__ float g_u_qo   [2048*64];
__device__ float g_v_qo   [2048*64];
__device__ float g_u_av   [2048*64];
__device__ float g_v_av   [2048*64];
__device__ float g_kq     [2048*64];
__device__ float g_kb     [2048];
__device__ float g_U      [2048*64];
__device__ float g_FmP    [2048*64];
__device__ float g_wo     [32768];
__device__ float g_G      [32768*64];
__device__ float g_Ct     [64*65];
__device__ float g_fb     [64];

__device__ __forceinline__ float leaky(float x){ return x > 0.f ? x : 0.01f*x; }

// w[64 out][in_n] -> wt[c*65 + t] (transposed, padded)
__device__ __forceinline__ void load_wT(const float* __restrict__ w, int in_n, float* wt){
    for (int idx = threadIdx.x; idx < 64*in_n; idx += NTHREADS) {
        int t = idx / in_n, c = idx - t*in_n;
        wt[c*65 + t] = w[idx];
    }
}

// 32 rows x 64 outs, 256 threads: thread owns out-col t, 8 rows in registers.
// in_s rows 16B-aligned (LDIN % 4 == 0), weights wT[c*65+t].
template<int CIN, int LDIN, bool LK>
__device__ __forceinline__ void gemm32(const float* __restrict__ in_s,
                                       const float* __restrict__ wT,
                                       const float* __restrict__ bias,
                                       float* __restrict__ out, int ldout)
{
    int t  = threadIdx.x & 63;
    int rg = threadIdx.x >> 6;
    float b = bias ? bias[t] : 0.f;
    float acc[8];
    #pragma unroll
    for (int k = 0; k < 8; k++) acc[k] = b;
    for (int c4 = 0; c4 < CIN/4; c4++) {
        float w0 = wT[(c4*4+0)*65 + t];
        float w1 = wT[(c4*4+1)*65 + t];
        float w2 = wT[(c4*4+2)*65 + t];
        float w3 = wT[(c4*4+3)*65 + t];
        #pragma unroll
        for (int k = 0; k < 8; k++) {
            float4 v = *reinterpret_cast<const float4*>(&in_s[(rg*8+k)*LDIN + c4*4]);
            acc[k] = fmaf(v.x, w0, fmaf(v.y, w1, fmaf(v.z, w2, fmaf(v.w, w3, acc[k]))));
        }
    }
    #pragma unroll
    for (int k = 0; k < 8; k++)
        out[(rg*8+k)*ldout + t] = LK ? leaky(acc[k]) : acc[k];
}

// ---------------- kA2: key_z / query_z, grid (64 tiles, 2 tasks) ----------------
__global__ void kA2(const float* __restrict__ obs,
                    const float* kw1, const float* kb1, const float* kw2, const float* kb2,
                    const float* qw1, const float* qb1, const float* qw2, const float* qb2)
{
    extern __shared__ float sm[];
    float* w1  = sm;           // 4160
    float* w2  = sm + 4160;    // 4160
    float* in_s = sm + 8320;   // 2048
    float* hid  = sm + 10368;  // 2048
    int task = blockIdx.y;
    const float *W1 = task ? qw1 : kw1, *B1 = task ? qb1 : kb1;
    const float *W2 = task ? qw2 : kw2, *B2 = task ? qb2 : kb2;
    float* outg = task ? g_query_z : g_key_z;
    load_wT(W1, 64, w1); load_wT(W2, 64, w2);
    int rb = blockIdx.x * 32;
    for (int idx = threadIdx.x; idx < 2048; idx += NTHREADS)
        in_s[idx] = obs[(size_t)rb*64 + idx];
    __syncthreads();
    gemm32<64,64,true >(in_s, w1, B1, hid, 64);
    __syncthreads();
    gemm32<64,64,false>(hid,  w2, B2, outg + (size_t)rb*64, 64);
}

// ---------------- kB: sigmoid attention weights w ----------------
__global__ void kB(float* __restrict__ out_wz)
{
    __shared__ float q_s[16*65], k_s[16*65];
    int b = blockIdx.x;
    for (int idx = threadIdx.x; idx < 1024; idx += NTHREADS) {
        int r = idx >> 6, c = idx & 63;
        q_s[r*65 + c] = g_query_z[b*1024 + idx];
        k_s[r*65 + c] = g_key_z  [b*1024 + idx];
    }
    __syncthreads();
    int i = threadIdx.x >> 4, j = threadIdx.x & 15;
    float acc = 0.f;
    #pragma unroll
    for (int d = 0; d < 64; d++) acc = fmaf(q_s[i*65 + d], k_s[j*65 + d], acc);
    float w = 1.f / (1.f + expf(-acc * 0.125f));
    g_w  [b*256 + threadIdx.x] = w;
    out_wz[b*256 + threadIdx.x] = w;
}

// ---------------- kCD: grid (64 tiles, 5 tasks) ----------------
// task 0: key_o = MLP_ko(src)    task 1: attn_src = MLP_av(src)
// task 2: P = MLP_av(op)         task 3: u_qo/v_qo (qo layer-1 split)
// task 4: u_av/v_av (av layer-1 split)
__global__ void kCD(const float* __restrict__ obs, const float* __restrict__ pol,
                    const float* __restrict__ act,
                    const float* ko1, const float* ko1b, const float* ko2, const float* ko2b,
                    const float* av1, const float* av1b, const float* av2, const float* av2b,
                    const float* qo1, const float* qo1b)
{
    extern __shared__ float sm[];
    float* w1   = sm;            // 4680
    float* w2   = sm + 4680;     // 4160
    float* in_s = sm + 8840;     // 32*72 = 2304
    float* hid  = sm + 11144;    // 2048 (also dl[256] for tasks 3/4)
    int task = blockIdx.y;
    int rb = blockIdx.x * 32;
    if (task <= 2) {
        const float* W1 = (task == 0) ? ko1  : av1;
        const float* B1 = (task == 0) ? ko1b : av1b;
        const float* W2 = (task == 0) ? ko2  : av2;
        const float* B2 = (task == 0) ? ko2b : av2b;
        float* outg = (task == 0) ? g_key_o : (task == 1) ? g_attn_src : g_P;
        load_wT(W1, 72, w1); load_wT(W2, 64, w2);
        for (int idx = threadIdx.x; idx < 32*72; idx += NTHREADS) {
            int r = idx / 72, c = idx - r*72;
            int g = rb + r;
            float v;
            if (c < 64) v = obs[(size_t)g*64 + c];
            else {
                int n = c - 64;
                float p = pol[g*8 + n];
                if (task == 2) v = p;
                else {
                    float wv = g_w[g*16 + (g & 15)];
                    v = fmaf(wv, act[g*8 + n] - p, p);
                }
            }
            in_s[idx] = v;
        }
        __syncthreads();
        gemm32<72,72,true >(in_s, w1, B1, hid, 64);
        __syncthreads();
        gemm32<64,64,false>(hid,  w2, B2, outg + (size_t)rb*64, 64);
    } else {
        const float* W1 = (task == 3) ? qo1  : av1;
        const float* B1 = (task == 3) ? qo1b : av1b;
        float* outu = (task == 3) ? g_u_qo : g_u_av;
        float* outv = (task == 3) ? g_v_qo : g_v_av;
        float* dl = hid;   // 32*8 = 256
        load_wT(W1, 72, w1);
        for (int idx = threadIdx.x; idx < 32*72; idx += NTHREADS) {
            int r = idx / 72, c = idx - r*72;
            in_s[idx] = (c < 64) ? obs[(size_t)(rb+r)*64 + c] : pol[(rb+r)*8 + c - 64];
        }
        for (int idx = threadIdx.x; idx < 256; idx += NTHREADS) {
            int r = idx >> 3, c = idx & 7;
            dl[idx] = act[(rb+r)*8 + c] - pol[(rb+r)*8 + c];
        }
        __syncthreads();
        gemm32<72,72,false>(in_s, w1,         B1,      outu + (size_t)rb*64, 64);
        gemm32< 8, 8,false>(dl,   w1 + 64*65, nullptr, outv + (size_t)rb*64, 64);
    }
}

// ---------------- kD22: grid (64 tiles, 3 tasks): kq(+kb), U, FmP ----------------
__global__ void kD22(const float* __restrict__ qo2, const float* __restrict__ qo2b,
                     const float* __restrict__ fv1, const float* __restrict__ fv1b)
{
    extern __shared__ float sm[];
    float* wT   = sm;           // 4160
    float* in_s = sm + 4160;    // 2048
    float* b2s  = sm + 6208;    // 64
    int task = blockIdx.y;
    int rb = blockIdx.x * 32;
    for (int idx = threadIdx.x; idx < 4096; idx += NTHREADS) {
        int c = idx >> 6, t = idx & 63;
        if (task == 0)      wT[c*65 + t] = qo2[idx];            // W2 (not transposed)
        else if (task == 1) wT[t*65 + c] = fv1[c*128 + t];      // fv1[:, :64]^T
        else                wT[t*65 + c] = fv1[c*128 + 64 + t]; // fv1[:, 64:]^T
    }
    if (task == 0 && threadIdx.x < 64) b2s[threadIdx.x] = qo2b[threadIdx.x];
    const float* src = (task == 0) ? g_key_o : (task == 1) ? g_attn_src : g_P;
    for (int idx = threadIdx.x; idx < 2048; idx += NTHREADS)
        in_s[idx] = src[(size_t)rb*64 + idx];
    __syncthreads();
    float* outg = (task == 0) ? g_kq : (task == 1) ? g_U : g_FmP;
    const float* bias = (task == 1) ? fv1b : nullptr;
    gemm32<64,64,false>(in_s, wT, bias, outg + (size_t)rb*64, 64);
    if (task == 0 && threadIdx.x < 32) {
        int r = threadIdx.x;
        float s = 0.f;
        for (int c = 0; c < 64; c++) {
            int cc = (c + r) & 63;                 // rotate vs bank conflicts
            s = fmaf(in_s[r*64 + cc], b2s[cc], s);
        }
        g_kb[rb + r] = s;
    }
}

// ---------------- kE: score_o (query_o never materialized) + softmax ----------------
__global__ void kE()
{
    __shared__ float kq_s[16*65], uq_s[16*65], vq_s[16*65], kb_s[16], w_s[256];
    int b = blockIdx.x;
    for (int idx = threadIdx.x; idx < 1024; idx += NTHREADS) {
        int r = idx >> 6, c = idx & 63;
        kq_s[r*65 + c] = g_kq  [b*1024 + idx];
        uq_s[r*65 + c] = g_u_qo[b*1024 + idx];
        vq_s[r*65 + c] = g_v_qo[b*1024 + idx];
    }
    if (threadIdx.x < 16) kb_s[threadIdx.x] = g_kb[b*16 + threadIdx.x];
    w_s[threadIdx.x] = g_w[b*256 + threadIdx.x];
    __syncthreads();
    int i = threadIdx.x >> 4, j = threadIdx.x & 15;
    float wv = w_s[threadIdx.x];
    float acc = kb_s[i];
    #pragma unroll
    for (int d = 0; d < 64; d++) {
        float h = leaky(fmaf(wv, vq_s[j*65 + d], uq_s[j*65 + d]));
        acc = fmaf(kq_s[i*65 + d], h, acc);
    }
    float sc = fminf(fmaxf(acc * 0.125f, -5.f), 5.f);
    float t = expf(sc);
    float mx = t;
    #pragma unroll
    for (int m = 1; m < 16; m <<= 1) mx = fmaxf(mx, __shfl_xor_sync(0xffffffffu, mx, m));
    float e = expf(t - mx), s = e;
    #pragma unroll
    for (int m = 1; m < 16; m <<= 1) s += __shfl_xor_sync(0xffffffffu, s, m);
    g_wo[b*256 + threadIdx.x] = e / s;
}

// ---------------- kF0: C^T = (Fm @ av2_w)^T, fb = Fm @ av2_b ----------------
__global__ void kF0(const float* __restrict__ fv1, const float* __restrict__ av2w,
                    const float* __restrict__ av2b)
{
    __shared__ float fm[64*64], w2t[64*65], b2[64];
    for (int idx = threadIdx.x; idx < 4096; idx += NTHREADS) {
        int t = idx >> 6, c = idx & 63;
        fm[idx] = fv1[t*128 + 64 + c];
        w2t[(idx & 63)*65 + (idx >> 6)] = av2w[idx];
    }
    if (threadIdx.x < 64) b2[threadIdx.x] = av2b[threadIdx.x];
    __syncthreads();
    for (int idx = threadIdx.x; idx < 4096; idx += NTHREADS) {
        int t = idx & 63, e = idx >> 6;
        float s = 0.f;
        for (int c = 0; c < 64; c++) {
            int cc = (c + t) & 63;
            s = fmaf(fm[t*64 + cc], w2t[e*65 + cc], s);
        }
        g_Ct[e*65 + t] = s;
    }
    if (threadIdx.x < 64) {
        int t = threadIdx.x;
        float s = 0.f;
        for (int c = 0; c < 64; c++) {
            int cc = (c + t) & 63;
            s = fmaf(fm[t*64 + cc], b2[cc], s);
        }
        g_fb[t] = s;
    }
}

// ---------------- kF: L = leaky(u + w*v); G = C @ L (grid 1024, 32 rows) ----------------
__global__ void kF()
{
    extern __shared__ float sm[];
    float* Ct_s = sm;            // 4160
    float* L_s  = sm + 4160;     // 2048
    float* u_s  = sm + 6208;     // 1024
    float* v_s  = sm + 7232;     // 1024
    float* w_s  = sm + 8256;     // 32
    int rb = blockIdx.x * 32;
    int b  = rb >> 8;
    for (int idx = threadIdx.x; idx < 4160; idx += NTHREADS) Ct_s[idx] = g_Ct[idx];
    for (int idx = threadIdx.x; idx < 1024; idx += NTHREADS) {
        u_s[idx] = g_u_av[b*1024 + idx];
        v_s[idx] = g_v_av[b*1024 + idx];
    }
    if (threadIdx.x < 32) w_s[threadIdx.x] = g_w[rb + threadIdx.x];
    __syncthreads();
    for (int idx = threadIdx.x; idx < 2048; idx += NTHREADS) {
        int r = idx >> 6, t = idx & 63;
        int j = (rb + r) & 15;
        L_s[idx] = leaky(fmaf(w_s[r], v_s[j*64 + t], u_s[j*64 + t]));
    }
    __syncthreads();
    gemm32<64,64,false>(L_s, Ct_s, nullptr, g_G + (size_t)rb*64, 64);
}

// ---------------- kG: value head ----------------
__global__ void kG(const float* __restrict__ fv2, const float* __restrict__ fv2b,
                   float* __restrict__ out_val)
{
    extern __shared__ float sm[];
    float* G_s   = sm;             // 16640
    float* U_s   = sm + 16640;     // 1040
    float* Fp_s  = sm + 17680;     // 1040
    float* fb_s  = sm + 18720;     // 64
    float* fv2_s = sm + 18784;     // 512
    float* wo_s  = sm + 19296;     // 256
    float* b2v   = sm + 19552;     // 8
    int b = blockIdx.x;
    for (int idx = threadIdx.x; idx < 16384; idx += NTHREADS) {
        int r = idx >> 6, c = idx & 63;
        G_s[r*65 + c] = g_G[(size_t)b*16384 + idx];
    }
    for (int idx = threadIdx.x; idx < 1024; idx += NTHREADS) {
        int r = idx >> 6, c = idx & 63;
        U_s [r*65 + c] = g_U  [b*1024 + idx];
        Fp_s[r*65 + c] = g_FmP[b*1024 + idx];
    }
    if (threadIdx.x < 64) fb_s[threadIdx.x] = g_fb[threadIdx.x];
    for (int idx = threadIdx.x; idx < 512; idx += NTHREADS) fv2_s[idx] = fv2[idx];
    wo_s[threadIdx.x] = g_wo[b*256 + threadIdx.x];
    if (threadIdx.x < 8) b2v[threadIdx.x] = fv2b[threadIdx.x];
    __syncthreads();
    int i = threadIdx.x >> 4, j = threadIdx.x & 15;
    float wo_r[16];
    #pragma unroll
    for (int k = 0; k < 16; k++) wo_r[k] = wo_s[j*16 + k];
    float wjj = wo_r[j];
    float vout[8];
    #pragma unroll
    for (int o = 0; o < 8; o++) vout[o] = b2v[o];
    for (int t = 0; t < 64; t++) {
        float m = 0.f;
        #pragma unroll
        for (int k = 0; k < 16; k++) m = fmaf(wo_r[k], G_s[(i*16 + k)*65 + t], m);
        float gij = G_s[(i*16 + j)*65 + t];
        float fbt = fb_s[t];
        float h = U_s[j*65 + t] + 0.0625f * (m + fbt + wjj * (Fp_s[j*65 + t] - gij - fbt));
        float ht = leaky(h);
        #pragma unroll
        for (int o = 0; o < 8; o++) vout[o] = fmaf(fv2_s[o*64 + t], ht, vout[o]);
    }
    float4* dst = reinterpret_cast<float4*>(out_val + (size_t)(b*256 + threadIdx.x)*8);
    dst[0] = make_float4(vout[0], vout[1], vout[2], vout[3]);
    dst[1] = make_float4(vout[4], vout[5], vout[6], vout[7]);
}

// ---------------- kH: weights_obsz broadcast ----------------
__global__ void kH(float4* __restrict__ out4)
{
    int q = blockIdx.x * NTHREADS + threadIdx.x;   // < 131072
    int idx = q << 2;
    const float4* wo4 = reinterpret_cast<const float4*>(g_wo);
    out4[q] = wo4[(((idx >> 12) << 8) | (idx & 255)) >> 2];
}

// ---------------- launcher ----------------
extern "C" void kernel_launch(void* const* d_in, const int* in_sizes, int n_in,
                              void* d_out, int out_size)
{
    const float* obs  = (const float*)d_in[0];
    const float* pol  = (const float*)d_in[1];
    const float* act  = (const float*)d_in[2];
    const float* kw1  = (const float*)d_in[3];  const float* kw1b = (const float*)d_in[4];
    const float* kw2  = (const float*)d_in[5];  const float* kw2b = (const float*)d_in[6];
    const float* qw1  = (const float*)d_in[7];  const float* qw1b = (const float*)d_in[8];
    const float* qw2  = (const float*)d_in[9];  const float* qw2b = (const float*)d_in[10];
    const float* ko1  = (const float*)d_in[11]; const float* ko1b = (const float*)d_in[12];
    const float* ko2  = (const float*)d_in[13]; const float* ko2b = (const float*)d_in[14];
    const float* qo1  = (const float*)d_in[15]; const float* qo1b = (const float*)d_in[16];
    const float* qo2  = (const float*)d_in[17]; const float* qo2b = (const float*)d_in[18];
    const float* av1  = (const float*)d_in[19]; const float* av1b = (const float*)d_in[20];
    const float* av2  = (const float*)d_in[21]; const float* av2b = (const float*)d_in[22];
    const float* fv1  = (const float*)d_in[23]; const float* fv1b = (const float*)d_in[24];
    const float* fv2  = (const float*)d_in[25]; const float* fv2b = (const float*)d_in[26];

    float* out      = (float*)d_out;
    float* out_val  = out;
    float* out_wz   = out + 262144;
    float* out_obsz = out + 294912;

    const int SMA2  = 12416 * 4;   // 49664
    const int SMCD  = 13192 * 4;   // 52768
    const int SMD22 =  6272 * 4;   // 25088
    const int SMF   =  8288 * 4;   // 33152
    const int SMG   = 19560 * 4;   // 78240

    cudaFuncSetAttribute(kA2,  cudaFuncAttributeMaxDynamicSharedMemorySize, SMA2);
    cudaFuncSetAttribute(kCD,  cudaFuncAttributeMaxDynamicSharedMemorySize, SMCD);
    cudaFuncSetAttribute(kD22, cudaFuncAttributeMaxDynamicSharedMemorySize, SMD22);
    cudaFuncSetAttribute(kF,   cudaFuncAttributeMaxDynamicSharedMemorySize, SMF);
    cudaFuncSetAttribute(kG,   cudaFuncAttributeMaxDynamicSharedMemorySize, SMG);

    kF0 <<<1,   NTHREADS       >>>(fv1, av2, av2b);               // independent
    kA2 <<<dim3(64,2), NTHREADS, SMA2 >>>(obs, kw1, kw1b, kw2, kw2b, qw1, qw1b, qw2, qw2b);
    kB  <<<128, NTHREADS       >>>(out_wz);
    kCD <<<dim3(64,5), NTHREADS, SMCD >>>(obs, pol, act, ko1, ko1b, ko2, ko2b,
                                          av1, av1b, av2, av2b, qo1, qo1b);
    kD22<<<dim3(64,3), NTHREADS, SMD22>>>(qo2, qo2b, fv1, fv1b);
    kF  <<<1024, NTHREADS, SMF >>>();
    kE  <<<128, NTHREADS       >>>();
    kG  <<<128, NTHREADS, SMG  >>>(fv2, fv2b, out_val);
    kH  <<<512, NTHREADS       >>>(reinterpret_cast<float4*>(out_obsz));
}

// round 6
// speedup vs baseline: 2.2342x; 1.1421x over previous
#include <cuda_runtime.h>
#include <math.h>

// A=16, NA=8, D_OBS=64, DZ=72, Bn=128. 2048 (b,agent) rows, 32768 (b,i,j) rows.
// Output: value[262144] | weight_z[32768] | weights_obsz[524288]

#define NTHREADS 256

// ---------------- intermediates ----------------
__device__ float g_key_z  [2048*64];
__device__ float g_query_z[2048*64];
__device__ float g_w      [32768];
__device__ float g_key_o  [2048*64];
__device__ float g_attn_src[2048*64];
__device__ float g_P      [2048*64];
__device__ float g_u_qo   [2048*64];
__device__ float g_v_qo   [2048*64];
__device__ float g_u_av   [2048*64];
__device__ float g_v_av   [2048*64];
__device__ float g_kq     [2048*64];
__device__ float g_kb     [2048];
__device__ float g_U      [2048*64];
__device__ float g_FmP    [2048*64];
__device__ float g_wo     [32768];
__device__ float g_G      [32768*64];
__device__ float g_Ct     [64*65];
__device__ float g_fb     [64];

__device__ __forceinline__ float leaky(float x){ return x > 0.f ? x : 0.01f*x; }

__device__ __forceinline__ void load_wT(const float* __restrict__ w, int in_n, float* wt){
    for (int idx = threadIdx.x; idx < 64*in_n; idx += NTHREADS) {
        int t = idx / in_n, c = idx - t*in_n;
        wt[c*65 + t] = w[idx];
    }
}

// 32 rows x 64 outs, 256 threads: thread owns out-col t, 8 rows in registers.
template<int CIN, int LDIN, bool LK>
__device__ __forceinline__ void gemm32(const float* __restrict__ in_s,
                                       const float* __restrict__ wT,
                                       const float* __restrict__ bias,
                                       float* __restrict__ out, int ldout)
{
    int t  = threadIdx.x & 63;
    int rg = threadIdx.x >> 6;
    float b = bias ? bias[t] : 0.f;
    float acc[8];
    #pragma unroll
    for (int k = 0; k < 8; k++) acc[k] = b;
    for (int c4 = 0; c4 < CIN/4; c4++) {
        float w0 = wT[(c4*4+0)*65 + t];
        float w1 = wT[(c4*4+1)*65 + t];
        float w2 = wT[(c4*4+2)*65 + t];
        float w3 = wT[(c4*4+3)*65 + t];
        #pragma unroll
        for (int k = 0; k < 8; k++) {
            float4 v = *reinterpret_cast<const float4*>(&in_s[(rg*8+k)*LDIN + c4*4]);
            acc[k] = fmaf(v.x, w0, fmaf(v.y, w1, fmaf(v.z, w2, fmaf(v.w, w3, acc[k]))));
        }
    }
    #pragma unroll
    for (int k = 0; k < 8; k++)
        out[(rg*8+k)*ldout + t] = LK ? leaky(acc[k]) : acc[k];
}

// ================= M1: kA2(key_z/query_z) x128 | P/uv x192 | kF0 x1 =================
__global__ void M1(const float* __restrict__ obs, const float* __restrict__ pol,
                   const float* __restrict__ act,
                   const float* kw1, const float* kb1, const float* kw2, const float* kb2,
                   const float* qw1, const float* qb1, const float* qw2, const float* qb2,
                   const float* qo1, const float* qo1b,
                   const float* av1, const float* av1b,
                   const float* av2w, const float* av2b, const float* fv1)
{
    extern __shared__ float sm[];
    int bx = blockIdx.x;
    if (bx < 128) {
        // ---- kA2: 2-layer 64->64->64 MLP on obs ----
        int task = bx >> 6, tile = bx & 63;
        float* w1   = sm;           // 4160
        float* w2   = sm + 4160;    // 4160
        float* in_s = sm + 8320;    // 2048
        float* hid  = sm + 10368;   // 2048
        const float *W1 = task ? qw1 : kw1, *B1 = task ? qb1 : kb1;
        const float *W2 = task ? qw2 : kw2, *B2 = task ? qb2 : kb2;
        float* outg = task ? g_query_z : g_key_z;
        load_wT(W1, 64, w1); load_wT(W2, 64, w2);
        int rb = tile * 32;
        for (int idx = threadIdx.x; idx < 2048; idx += NTHREADS)
            in_s[idx] = obs[(size_t)rb*64 + idx];
        __syncthreads();
        gemm32<64,64,true >(in_s, w1, B1, hid, 64);
        __syncthreads();
        gemm32<64,64,false>(hid,  w2, B2, outg + (size_t)rb*64, 64);
    } else if (bx < 320) {
        int u = bx - 128;
        int sub = u >> 6, tile = u & 63;   // 0:P  1:qo u/v  2:av u/v
        int rb = tile * 32;
        if (sub == 0) {
            float* w1   = sm;            // 4680
            float* w2   = sm + 4680;     // 4160
            float* in_s = sm + 8840;     // 2304
            float* hid  = sm + 11144;    // 2048
            load_wT(av1, 72, w1); load_wT(av2w, 64, w2);
            for (int idx = threadIdx.x; idx < 32*72; idx += NTHREADS) {
                int r = idx / 72, c = idx - r*72;
                in_s[idx] = (c < 64) ? obs[(size_t)(rb+r)*64 + c] : pol[(rb+r)*8 + c - 64];
            }
            __syncthreads();
            gemm32<72,72,true >(in_s, w1, av1b, hid, 64);
            __syncthreads();
            gemm32<64,64,false>(hid,  w2, av2b, g_P + (size_t)rb*64, 64);
        } else {
            const float* W1 = (sub == 1) ? qo1  : av1;
            const float* B1 = (sub == 1) ? qo1b : av1b;
            float* outu = (sub == 1) ? g_u_qo : g_u_av;
            float* outv = (sub == 1) ? g_v_qo : g_v_av;
            float* w1   = sm;            // 4680
            float* in_s = sm + 4680;     // 2304
            float* dl   = sm + 6984;     // 256
            load_wT(W1, 72, w1);
            for (int idx = threadIdx.x; idx < 32*72; idx += NTHREADS) {
                int r = idx / 72, c = idx - r*72;
                in_s[idx] = (c < 64) ? obs[(size_t)(rb+r)*64 + c] : pol[(rb+r)*8 + c - 64];
            }
            for (int idx = threadIdx.x; idx < 256; idx += NTHREADS) {
                int r = idx >> 3, c = idx & 7;
                dl[idx] = act[(rb+r)*8 + c] - pol[(rb+r)*8 + c];
            }
            __syncthreads();
            gemm32<72,72,false>(in_s, w1,         B1,      outu + (size_t)rb*64, 64);
            gemm32< 8, 8,false>(dl,   w1 + 64*65, nullptr, outv + (size_t)rb*64, 64);
        }
    } else {
        // ---- kF0: Ct = (Fm @ av2w)^T, fb = Fm @ av2b ----
        float* fm  = sm;           // 4096
        float* w2t = sm + 4096;    // 4160
        float* b2  = sm + 8256;    // 64
        for (int idx = threadIdx.x; idx < 4096; idx += NTHREADS) {
            int t = idx >> 6, c = idx & 63;
            fm[idx] = fv1[t*128 + 64 + c];
            w2t[(idx & 63)*65 + (idx >> 6)] = av2w[idx];
        }
        if (threadIdx.x < 64) b2[threadIdx.x] = av2b[threadIdx.x];
        __syncthreads();
        for (int idx = threadIdx.x; idx < 4096; idx += NTHREADS) {
            int t = idx & 63, e = idx >> 6;
            float s = 0.f;
            for (int c = 0; c < 64; c++) {
                int cc = (c + t) & 63;
                s = fmaf(fm[t*64 + cc], w2t[e*65 + cc], s);
            }
            g_Ct[e*65 + t] = s;
        }
        if (threadIdx.x < 64) {
            int t = threadIdx.x;
            float s = 0.f;
            for (int c = 0; c < 64; c++) {
                int cc = (c + t) & 63;
                s = fmaf(fm[t*64 + cc], b2[cc], s);
            }
            g_fb[t] = s;
        }
    }
}

// ================= M2: key_o/attn_src x128 (diag-w in-block) | kB x128 =================
__global__ void M2(const float* __restrict__ obs, const float* __restrict__ pol,
                   const float* __restrict__ act,
                   const float* ko1, const float* ko1b, const float* ko2, const float* ko2b,
                   const float* av1, const float* av1b, const float* av2w, const float* av2b,
                   float* __restrict__ out_wz)
{
    extern __shared__ float sm[];
    int bx = blockIdx.x;
    if (bx < 128) {
        int net = bx >> 6, tile = bx & 63;
        float* w1    = sm;            // 4680
        float* w2    = sm + 4680;     // 4160
        float* in_s  = sm + 8840;     // 2304
        float* hid   = sm + 11144;    // 2048
        float* wdiag = sm + 13192;    // 32
        const float* W1 = net ? av1  : ko1;
        const float* B1 = net ? av1b : ko1b;
        const float* W2 = net ? av2w : ko2;
        const float* B2 = net ? av2b : ko2b;
        float* outg = net ? g_attn_src : g_key_o;
        int rb = tile * 32;
        load_wT(W1, 72, w1); load_wT(W2, 64, w2);
        if (threadIdx.x < 32) {
            int g = rb + threadIdx.x;
            const float4* kz = reinterpret_cast<const float4*>(g_key_z   + (size_t)g*64);
            const float4* qz = reinterpret_cast<const float4*>(g_query_z + (size_t)g*64);
            float s = 0.f;
            #pragma unroll
            for (int c = 0; c < 16; c++) {
                float4 a = kz[c], b = qz[c];
                s = fmaf(a.x,b.x, fmaf(a.y,b.y, fmaf(a.z,b.z, fmaf(a.w,b.w, s))));
            }
            wdiag[threadIdx.x] = 1.f / (1.f + expf(-s * 0.125f));
        }
        __syncthreads();
        for (int idx = threadIdx.x; idx < 32*72; idx += NTHREADS) {
            int r = idx / 72, c = idx - r*72;
            int g = rb + r;
            float v;
            if (c < 64) v = obs[(size_t)g*64 + c];
            else {
                int n = c - 64;
                float p = pol[g*8 + n];
                v = fmaf(wdiag[r], act[g*8 + n] - p, p);
            }
            in_s[idx] = v;
        }
        __syncthreads();
        gemm32<72,72,true >(in_s, w1, B1, hid, 64);
        __syncthreads();
        gemm32<64,64,false>(hid,  w2, B2, outg + (size_t)rb*64, 64);
    } else {
        // ---- kB: full sigmoid weights w[b,i,j] ----
        float* q_s = sm;            // 1040
        float* k_s = sm + 1040;     // 1040
        int b = bx - 128;
        for (int idx = threadIdx.x; idx < 1024; idx += NTHREADS) {
            int r = idx >> 6, c = idx & 63;
            q_s[r*65 + c] = g_query_z[b*1024 + idx];
            k_s[r*65 + c] = g_key_z  [b*1024 + idx];
        }
        __syncthreads();
        int i = threadIdx.x >> 4, j = threadIdx.x & 15;
        float acc = 0.f;
        #pragma unroll
        for (int d = 0; d < 64; d++) acc = fmaf(q_s[i*65 + d], k_s[j*65 + d], acc);
        float w = 1.f / (1.f + expf(-acc * 0.125f));
        g_w  [b*256 + threadIdx.x] = w;
        out_wz[b*256 + threadIdx.x] = w;
    }
}

// ================= M3: kD22 x192 | kF x1024 =================
__global__ void M3(const float* __restrict__ qo2, const float* __restrict__ qo2b,
                   const float* __restrict__ fv1, const float* __restrict__ fv1b)
{
    extern __shared__ float sm[];
    int bx = blockIdx.x;
    if (bx < 192) {
        // ---- kD22: kq(+kb) / U / FmP ----
        int task = bx >> 6, tile = bx & 63;
        float* wT   = sm;           // 4160
        float* in_s = sm + 4160;    // 2048
        float* b2s  = sm + 6208;    // 64
        int rb = tile * 32;
        for (int idx = threadIdx.x; idx < 4096; idx += NTHREADS) {
            int c = idx >> 6, t = idx & 63;
            if (task == 0)      wT[c*65 + t] = qo2[idx];
            else if (task == 1) wT[t*65 + c] = fv1[c*128 + t];
            else                wT[t*65 + c] = fv1[c*128 + 64 + t];
        }
        if (task == 0 && threadIdx.x < 64) b2s[threadIdx.x] = qo2b[threadIdx.x];
        const float* src = (task == 0) ? g_key_o : (task == 1) ? g_attn_src : g_P;
        for (int idx = threadIdx.x; idx < 2048; idx += NTHREADS)
            in_s[idx] = src[(size_t)rb*64 + idx];
        __syncthreads();
        float* outg = (task == 0) ? g_kq : (task == 1) ? g_U : g_FmP;
        const float* bias = (task == 1) ? fv1b : nullptr;
        gemm32<64,64,false>(in_s, wT, bias, outg + (size_t)rb*64, 64);
        if (task == 0 && threadIdx.x < 32) {
            int r = threadIdx.x;
            float s = 0.f;
            for (int c = 0; c < 64; c++) {
                int cc = (c + r) & 63;
                s = fmaf(in_s[r*64 + cc], b2s[cc], s);
            }
            g_kb[rb + r] = s;
        }
    } else {
        // ---- kF: L = leaky(u + w*v); G = C @ L ----
        float* Ct_s = sm;            // 4160
        float* L_s  = sm + 4160;     // 2048
        float* u_s  = sm + 6208;     // 1024
        float* v_s  = sm + 7232;     // 1024
        float* w_s  = sm + 8256;     // 32
        int rb = (bx - 192) * 32;
        int b  = rb >> 8;
        for (int idx = threadIdx.x; idx < 4160; idx += NTHREADS) Ct_s[idx] = g_Ct[idx];
        for (int idx = threadIdx.x; idx < 1024; idx += NTHREADS) {
            u_s[idx] = g_u_av[b*1024 + idx];
            v_s[idx] = g_v_av[b*1024 + idx];
        }
        if (threadIdx.x < 32) w_s[threadIdx.x] = g_w[rb + threadIdx.x];
        __syncthreads();
        for (int idx = threadIdx.x; idx < 2048; idx += NTHREADS) {
            int r = idx >> 6, t = idx & 63;
            int j = (rb + r) & 15;
            L_s[idx] = leaky(fmaf(w_s[r], v_s[j*64 + t], u_s[j*64 + t]));
        }
        __syncthreads();
        gemm32<64,64,false>(L_s, Ct_s, nullptr, g_G + (size_t)rb*64, 64);
    }
}

// ================= M4: kE (score_o + softmax) =================
__global__ void kE()
{
    __shared__ float kq_s[16*65], uq_s[16*65], vq_s[16*65], kb_s[16], w_s[256];
    int b = blockIdx.x;
    for (int idx = threadIdx.x; idx < 1024; idx += NTHREADS) {
        int r = idx >> 6, c = idx & 63;
        kq_s[r*65 + c] = g_kq  [b*1024 + idx];
        uq_s[r*65 + c] = g_u_qo[b*1024 + idx];
        vq_s[r*65 + c] = g_v_qo[b*1024 + idx];
    }
    if (threadIdx.x < 16) kb_s[threadIdx.x] = g_kb[b*16 + threadIdx.x];
    w_s[threadIdx.x] = g_w[b*256 + threadIdx.x];
    __syncthreads();
    int i = threadIdx.x >> 4, j = threadIdx.x & 15;
    float wv = w_s[threadIdx.x];
    float acc = kb_s[i];
    #pragma unroll
    for (int d = 0; d < 64; d++) {
        float h = leaky(fmaf(wv, vq_s[j*65 + d], uq_s[j*65 + d]));
        acc = fmaf(kq_s[i*65 + d], h, acc);
    }
    float sc = fminf(fmaxf(acc * 0.125f, -5.f), 5.f);
    float t = expf(sc);
    float mx = t;
    #pragma unroll
    for (int m = 1; m < 16; m <<= 1) mx = fmaxf(mx, __shfl_xor_sync(0xffffffffu, mx, m));
    float e = expf(t - mx), s = e;
    #pragma unroll
    for (int m = 1; m < 16; m <<= 1) s += __shfl_xor_sync(0xffffffffu, s, m);
    g_wo[b*256 + threadIdx.x] = e / s;
}

// ================= M5: kG x128 | kH x512 =================
__global__ void M5(const float* __restrict__ fv2, const float* __restrict__ fv2b,
                   float* __restrict__ out_val, float4* __restrict__ out4)
{
    extern __shared__ float sm[];
    int bx = blockIdx.x;
    if (bx < 128) {
        float* G_s   = sm;             // 16640
        float* U_s   = sm + 16640;     // 1040
        float* Fp_s  = sm + 17680;     // 1040
        float* fb_s  = sm + 18720;     // 64
        float* fv2_s = sm + 18784;     // 512
        float* wo_s  = sm + 19296;     // 256
        float* b2v   = sm + 19552;     // 8
        int b = bx;
        for (int idx = threadIdx.x; idx < 16384; idx += NTHREADS) {
            int r = idx >> 6, c = idx & 63;
            G_s[r*65 + c] = g_G[(size_t)b*16384 + idx];
        }
        for (int idx = threadIdx.x; idx < 1024; idx += NTHREADS) {
            int r = idx >> 6, c = idx & 63;
            U_s [r*65 + c] = g_U  [b*1024 + idx];
            Fp_s[r*65 + c] = g_FmP[b*1024 + idx];
        }
        if (threadIdx.x < 64) fb_s[threadIdx.x] = g_fb[threadIdx.x];
        for (int idx = threadIdx.x; idx < 512; idx += NTHREADS) fv2_s[idx] = fv2[idx];
        wo_s[threadIdx.x] = g_wo[b*256 + threadIdx.x];
        if (threadIdx.x < 8) b2v[threadIdx.x] = fv2b[threadIdx.x];
        __syncthreads();
        int i = threadIdx.x >> 4, j = threadIdx.x & 15;
        float wo_r[16];
        #pragma unroll
        for (int k = 0; k < 16; k++) wo_r[k] = wo_s[j*16 + k];
        float wjj = wo_r[j];
        float vout[8];
        #pragma unroll
        for (int o = 0; o < 8; o++) vout[o] = b2v[o];
        for (int t = 0; t < 64; t++) {
            float m = 0.f;
            #pragma unroll
            for (int k = 0; k < 16; k++) m = fmaf(wo_r[k], G_s[(i*16 + k)*65 + t], m);
            float gij = G_s[(i*16 + j)*65 + t];
            float fbt = fb_s[t];
            float h = U_s[j*65 + t] + 0.0625f * (m + fbt + wjj * (Fp_s[j*65 + t] - gij - fbt));
            float ht = leaky(h);
            #pragma unroll
            for (int o = 0; o < 8; o++) vout[o] = fmaf(fv2_s[o*64 + t], ht, vout[o]);
        }
        float4* dst = reinterpret_cast<float4*>(out_val + (size_t)(b*256 + threadIdx.x)*8);
        dst[0] = make_float4(vout[0], vout[1], vout[2], vout[3]);
        dst[1] = make_float4(vout[4], vout[5], vout[6], vout[7]);
    } else {
        int q = (bx - 128) * NTHREADS + threadIdx.x;   // < 131072
        int idx = q << 2;
        const float4* wo4 = reinterpret_cast<const float4*>(g_wo);
        out4[q] = wo4[(((idx >> 12) << 8) | (idx & 255)) >> 2];
    }
}

// ---------------- launcher ----------------
extern "C" void kernel_launch(void* const* d_in, const int* in_sizes, int n_in,
                              void* d_out, int out_size)
{
    const float* obs  = (const float*)d_in[0];
    const float* pol  = (const float*)d_in[1];
    const float* act  = (const float*)d_in[2];
    const float* kw1  = (const float*)d_in[3];  const float* kw1b = (const float*)d_in[4];
    const float* kw2  = (const float*)d_in[5];  const float* kw2b = (const float*)d_in[6];
    const float* qw1  = (const float*)d_in[7];  const float* qw1b = (const float*)d_in[8];
    const float* qw2  = (const float*)d_in[9];  const float* qw2b = (const float*)d_in[10];
    const float* ko1  = (const float*)d_in[11]; const float* ko1b = (const float*)d_in[12];
    const float* ko2  = (const float*)d_in[13]; const float* ko2b = (const float*)d_in[14];
    const float* qo1  = (const float*)d_in[15]; const float* qo1b = (const float*)d_in[16];
    const float* qo2  = (const float*)d_in[17]; const float* qo2b = (const float*)d_in[18];
    const float* av1  = (const float*)d_in[19]; const float* av1b = (const float*)d_in[20];
    const float* av2  = (const float*)d_in[21]; const float* av2b = (const float*)d_in[22];
    const float* fv1  = (const float*)d_in[23]; const float* fv1b = (const float*)d_in[24];
    const float* fv2  = (const float*)d_in[25]; const float* fv2b = (const float*)d_in[26];

    float* out      = (float*)d_out;
    float* out_val  = out;
    float* out_wz   = out + 262144;
    float* out_obsz = out + 294912;

    const int SM1 = 13192 * 4;   // 52768
    const int SM2 = 13224 * 4;   // 52896
    const int SM3 =  8288 * 4;   // 33152
    const int SM5 = 19560 * 4;   // 78240

    cudaFuncSetAttribute(M1, cudaFuncAttributeMaxDynamicSharedMemorySize, SM1);
    cudaFuncSetAttribute(M2, cudaFuncAttributeMaxDynamicSharedMemorySize, SM2);
    cudaFuncSetAttribute(M3, cudaFuncAttributeMaxDynamicSharedMemorySize, SM3);
    cudaFuncSetAttribute(M5, cudaFuncAttributeMaxDynamicSharedMemorySize, SM5);

    M1<<<321,  NTHREADS, SM1>>>(obs, pol, act, kw1, kw1b, kw2, kw2b,
                                qw1, qw1b, qw2, qw2b, qo1, qo1b, av1, av1b,
                                av2, av2b, fv1);
    M2<<<256,  NTHREADS, SM2>>>(obs, pol, act, ko1, ko1b, ko2, ko2b,
                                av1, av1b, av2, av2b, out_wz);
    M3<<<1216, NTHREADS, SM3>>>(qo2, qo2b, fv1, fv1b);
    kE<<<128,  NTHREADS     >>>();
    M5<<<640,  NTHREADS, SM5>>>(fv2, fv2b, out_val,
                                reinterpret_cast<float4*>(out_obsz));
}

// round 7
// speedup vs baseline: 2.2875x; 1.0239x over previous
#include <cuda_runtime.h>
#include <math.h>

// A=16, NA=8, D_OBS=64, DZ=72, Bn=128.
// Output: value[262144] | weight_z[32768] | weights_obsz[524288]

#define NTHREADS 256

// ---------------- cross-launch intermediates (per (b,agent) only) ----------------
__device__ float g_w   [32768];      // sigmoid w[b,i,j]
__device__ float g_wo  [32768];      // softmax weights_o[b,i,j]
__device__ float g_u_av[2048*64];
__device__ float g_v_av[2048*64];
__device__ float g_U   [2048*64];
__device__ float g_FmP [2048*64];
__device__ float g_Ct  [64*65];
__device__ float g_fb  [64];

__device__ __forceinline__ float leaky(float x){ return x > 0.f ? x : 0.01f*x; }

// w[64 out][in_n] row-major -> wt[c*65 + t] (transposed, padded)
__device__ __forceinline__ void load_wT(const float* __restrict__ w, int in_n, float* wt){
    for (int idx = threadIdx.x; idx < 64*in_n; idx += NTHREADS) {
        int t = idx / in_n, c = idx - t*in_n;
        wt[c*65 + t] = w[idx];
    }
}

// 16 rows x 64 outs, 256 threads: thread owns col t, row-group rg of 4 rows.
template<int CIN, int LDIN, bool LK>
__device__ __forceinline__ void gemm16(const float* __restrict__ in_s,
                                       const float* __restrict__ wT,
                                       const float* __restrict__ bias,
                                       float* __restrict__ out, int ldout)
{
    int t  = threadIdx.x & 63;
    int rg = threadIdx.x >> 6;
    float b = bias ? bias[t] : 0.f;
    float acc[4];
    #pragma unroll
    for (int k = 0; k < 4; k++) acc[k] = b;
    #pragma unroll
    for (int c4 = 0; c4 < CIN/4; c4++) {
        float w0 = wT[(c4*4+0)*65 + t];
        float w1 = wT[(c4*4+1)*65 + t];
        float w2 = wT[(c4*4+2)*65 + t];
        float w3 = wT[(c4*4+3)*65 + t];
        #pragma unroll
        for (int k = 0; k < 4; k++) {
            float4 v = *reinterpret_cast<const float4*>(&in_s[(rg*4+k)*LDIN + c4*4]);
            acc[k] = fmaf(v.x, w0, fmaf(v.y, w1, fmaf(v.z, w2, fmaf(v.w, w3, acc[k]))));
        }
    }
    #pragma unroll
    for (int k = 0; k < 4; k++)
        out[(rg*4+k)*ldout + t] = LK ? leaky(acc[k]) : acc[k];
}

// 32 rows x 64 outs (for L2's G build)
template<int CIN, int LDIN, bool LK>
__device__ __forceinline__ void gemm32(const float* __restrict__ in_s,
                                       const float* __restrict__ wT,
                                       const float* __restrict__ bias,
                                       float* __restrict__ out, int ldout)
{
    int t  = threadIdx.x & 63;
    int rg = threadIdx.x >> 6;
    float b = bias ? bias[t] : 0.f;
    float acc[8];
    #pragma unroll
    for (int k = 0; k < 8; k++) acc[k] = b;
    #pragma unroll
    for (int c4 = 0; c4 < CIN/4; c4++) {
        float w0 = wT[(c4*4+0)*65 + t];
        float w1 = wT[(c4*4+1)*65 + t];
        float w2 = wT[(c4*4+2)*65 + t];
        float w3 = wT[(c4*4+3)*65 + t];
        #pragma unroll
        for (int k = 0; k < 8; k++) {
            float4 v = *reinterpret_cast<const float4*>(&in_s[(rg*8+k)*LDIN + c4*4]);
            acc[k] = fmaf(v.x, w0, fmaf(v.y, w1, fmaf(v.z, w2, fmaf(v.w, w3, acc[k]))));
        }
    }
    #pragma unroll
    for (int k = 0; k < 8; k++)
        out[(rg*8+k)*ldout + t] = LK ? leaky(acc[k]) : acc[k];
}

// ================= L1: one block per batch b computes all agent-level tensors =================
// block 128: kF0 (Ct = (Fm @ av2w)^T-ish layout, fb = Fm @ av2b)
__global__ void L1(const float* __restrict__ obs, const float* __restrict__ pol,
                   const float* __restrict__ act,
                   const float* kw1, const float* kb1, const float* kw2, const float* kb2,
                   const float* qw1, const float* qb1, const float* qw2, const float* qb2,
                   const float* ko1, const float* ko1b, const float* ko2, const float* ko2b,
                   const float* qo1, const float* qo1b, const float* qo2, const float* qo2b,
                   const float* av1, const float* av1b, const float* av2w, const float* av2b,
                   const float* fv1, const float* fv1b,
                   float* __restrict__ out_wz)
{
    extern __shared__ float sm[];
    int bx = blockIdx.x;
    int tid = threadIdx.x;

    if (bx == 128) {
        // ---- kF0 ----
        float* fm  = sm;           // 4096
        float* w2t = sm + 4096;    // 4160
        float* b2  = sm + 8256;    // 64
        for (int idx = tid; idx < 4096; idx += NTHREADS) {
            int t = idx >> 6, c = idx & 63;
            fm[idx] = fv1[t*128 + 64 + c];
            w2t[(idx & 63)*65 + (idx >> 6)] = av2w[idx];
        }
        if (tid < 64) b2[tid] = av2b[tid];
        __syncthreads();
        for (int idx = tid; idx < 4096; idx += NTHREADS) {
            int t = idx & 63, e = idx >> 6;
            float s = 0.f;
            for (int c = 0; c < 64; c++) {
                int cc = (c + t) & 63;
                s = fmaf(fm[t*64 + cc], w2t[e*65 + cc], s);
            }
            g_Ct[e*65 + t] = s;
        }
        if (tid < 64) {
            float s = 0.f;
            for (int c = 0; c < 64; c++) {
                int cc = (c + tid) & 63;
                s = fmaf(fm[tid*64 + cc], b2[cc], s);
            }
            g_fb[tid] = s;
        }
        return;
    }

    int b = bx;
    // smem layout (floats)
    float* wA    = sm;             // 4680
    float* wB    = sm + 4680;      // 4680
    float* obs16 = sm + 9360;      // 1024
    float* pol16 = sm + 10384;     // 128
    float* dl    = sm + 10512;     // 128
    float* src   = sm + 10640;     // 1152
    float* op    = sm + 11792;     // 1152
    float* hid   = sm + 12944;     // 1024
    float* kz    = sm + 13968;     // 1024
    float* qz    = sm + 14992;     // 1024
    float* keyo  = sm + 16016;     // 1024
    float* atts  = sm + 17040;     // 1024
    float* Ps    = sm + 18064;     // 1024
    float* uav   = sm + 19088;     // 1024
    float* vav   = sm + 20112;     // 1024
    float* uqo   = sm + 21136;     // 1024
    float* vqo   = sm + 22160;     // 1024
    float* kq    = sm + 23184;     // 1024
    float* kb_s  = sm + 24208;     // 16
    float* w_sm  = sm + 24224;     // 256
    // total 24480 floats = 97920 B

    int i = tid >> 4, j = tid & 15;

    // inputs
    for (int idx = tid; idx < 1024; idx += NTHREADS) obs16[idx] = obs[(size_t)b*1024 + idx];
    if (tid < 128) {
        float p = pol[b*128 + tid];
        pol16[tid] = p;
        dl[tid]    = act[b*128 + tid] - p;
    }

    // ---- kz ----
    load_wT(kw1, 64, wA); load_wT(kw2, 64, wB);
    __syncthreads();
    gemm16<64,64,true >(obs16, wA, kb1, hid, 64);
    __syncthreads();
    gemm16<64,64,false>(hid,   wB, kb2, kz, 64);
    __syncthreads();
    // ---- qz ----
    load_wT(qw1, 64, wA); load_wT(qw2, 64, wB);
    __syncthreads();
    gemm16<64,64,true >(obs16, wA, qb1, hid, 64);
    __syncthreads();
    gemm16<64,64,false>(hid,   wB, qb2, qz, 64);
    __syncthreads();

    // ---- w[i,j] = sigmoid(qz[i].kz[j] / 8) ----
    {
        float acc = 0.f;
        #pragma unroll
        for (int d = 0; d < 64; d++) {
            int dd = (d + 2*j) & 63;
            acc = fmaf(qz[i*64 + dd], kz[j*64 + dd], acc);
        }
        float w = 1.f / (1.f + expf(-acc * 0.125f));
        w_sm[tid] = w;
        g_w[b*256 + tid] = w;
        out_wz[b*256 + tid] = w;
    }
    __syncthreads();

    // ---- src / op rows (72-wide) ----
    for (int idx = tid; idx < 1152; idx += NTHREADS) {
        int r = idx / 72, c = idx - r*72;
        float vs, vo;
        if (c < 64) { float o = obs16[r*64 + c]; vs = o; vo = o; }
        else {
            int n = c - 64;
            float p = pol16[r*8 + n];
            vs = fmaf(w_sm[r*17], dl[r*8 + n], p);   // w[r,r]
            vo = p;
        }
        src[idx] = vs; op[idx] = vo;
    }
    // ---- key_o ----
    load_wT(ko1, 72, wA); load_wT(ko2, 64, wB);
    __syncthreads();
    gemm16<72,72,true >(src, wA, ko1b, hid, 64);
    __syncthreads();
    gemm16<64,64,false>(hid, wB, ko2b, keyo, 64);
    __syncthreads();
    // ---- av net: atts (src), u_av/v_av (op split), P ----
    load_wT(av1, 72, wA); load_wT(av2w, 64, wB);
    __syncthreads();
    gemm16<72,72,true >(src, wA, av1b, hid, 64);
    __syncthreads();
    gemm16<64,64,false>(hid, wB, av2b, atts, 64);
    gemm16<72,72,false>(op,  wA, av1b, uav, 64);                 // pre-activation
    gemm16< 8, 8,false>(dl,  wA + 64*65, nullptr, vav, 64);
    __syncthreads();
    for (int idx = tid; idx < 1024; idx += NTHREADS) hid[idx] = leaky(uav[idx]);
    __syncthreads();
    gemm16<64,64,false>(hid, wB, av2b, Ps, 64);
    __syncthreads();
    // ---- qo layer-1 split ----
    load_wT(qo1, 72, wA);
    __syncthreads();
    gemm16<72,72,false>(op, wA, qo1b, uqo, 64);
    gemm16< 8, 8,false>(dl, wA + 64*65, nullptr, vqo, 64);
    __syncthreads();
    // ---- kq = keyo @ W2qo (non-transposed layout), kb = keyo . qo2b ----
    for (int idx = tid; idx < 4096; idx += NTHREADS) {
        int c = idx >> 6, t = idx & 63;
        wB[c*65 + t] = qo2[idx];
    }
    __syncthreads();
    gemm16<64,64,false>(keyo, wB, nullptr, kq, 64);
    if (tid < 16) {
        float s = 0.f;
        for (int c = 0; c < 64; c++) {
            int cc = (c + 4*tid) & 63;
            s = fmaf(keyo[tid*64 + cc], qo2b[cc], s);
        }
        kb_s[tid] = s;
    }
    __syncthreads();
    // ---- U = atts@fv1a^T + fv1b, FmP = P@Fm^T (to global) ----
    for (int idx = tid; idx < 4096; idx += NTHREADS) {
        int t = idx >> 6, c = idx & 63;
        wA[c*65 + t] = fv1[t*128 + c];
        wB[c*65 + t] = fv1[t*128 + 64 + c];
    }
    __syncthreads();
    gemm16<64,64,false>(atts, wA, fv1b, g_U   + b*1024, 64);
    gemm16<64,64,false>(Ps,   wB, nullptr, g_FmP + b*1024, 64);
    for (int idx = tid; idx < 1024; idx += NTHREADS) {
        g_u_av[b*1024 + idx] = uav[idx];
        g_v_av[b*1024 + idx] = vav[idx];
    }
    // ---- kE: wo softmax (local) ----
    {
        float wv = w_sm[tid];
        float acc = kb_s[i];
        #pragma unroll
        for (int d = 0; d < 64; d++) {
            int dd = (d + 2*j) & 63;
            float h = leaky(fmaf(wv, vqo[j*64 + dd], uqo[j*64 + dd]));
            acc = fmaf(kq[i*64 + dd], h, acc);
        }
        float sc = fminf(fmaxf(acc * 0.125f, -5.f), 5.f);
        float t = expf(sc);
        float mx = t;
        #pragma unroll
        for (int m = 1; m < 16; m <<= 1) mx = fmaxf(mx, __shfl_xor_sync(0xffffffffu, mx, m));
        float e = expf(t - mx), s = e;
        #pragma unroll
        for (int m = 1; m < 16; m <<= 1) s += __shfl_xor_sync(0xffffffffu, s, m);
        g_wo[b*256 + tid] = e / s;
    }
}

// ================= L2: per-batch fused kF+kG + weights_obsz write =================
__global__ void L2(const float* __restrict__ fv2, const float* __restrict__ fv2b,
                   float* __restrict__ out_val, float4* __restrict__ out4)
{
    extern __shared__ float sm[];
    float* Ct_s  = sm;             // 4160
    float* L_s   = sm + 4160;      // 16384
    float* G_s   = sm + 20544;     // 16640
    float* u_s   = sm + 37184;     // 1024
    float* v_s   = sm + 38208;     // 1024
    float* w_s   = sm + 39232;     // 256
    float* U_s   = sm + 39488;     // 1040
    float* Fp_s  = sm + 40528;     // 1040
    float* fb_s  = sm + 41568;     // 64
    float* fv2_s = sm + 41632;     // 512
    float* wo_s  = sm + 42144;     // 256
    float* b2v   = sm + 42400;     // 8
    // total 42408 floats = 169632 B

    int b = blockIdx.x;
    int tid = threadIdx.x;
    for (int idx = tid; idx < 4160; idx += NTHREADS) Ct_s[idx] = g_Ct[idx];
    for (int idx = tid; idx < 1024; idx += NTHREADS) {
        u_s[idx] = g_u_av[b*1024 + idx];
        v_s[idx] = g_v_av[b*1024 + idx];
        int r = idx >> 6, c = idx & 63;
        U_s [r*65 + c] = g_U  [b*1024 + idx];
        Fp_s[r*65 + c] = g_FmP[b*1024 + idx];
    }
    w_s [tid] = g_w [b*256 + tid];
    wo_s[tid] = g_wo[b*256 + tid];
    if (tid < 64) fb_s[tid] = g_fb[tid];
    for (int idx = tid; idx < 512; idx += NTHREADS) fv2_s[idx] = fv2[idx];
    if (tid < 8) b2v[tid] = fv2b[tid];
    __syncthreads();
    // L[(i,j), t] = leaky(u_av[j,t] + w[i,j] * v_av[j,t])
    for (int idx = tid; idx < 16384; idx += NTHREADS) {
        int r = idx >> 6, t = idx & 63;
        int j = r & 15;
        L_s[idx] = leaky(fmaf(w_s[r], v_s[j*64 + t], u_s[j*64 + t]));
    }
    __syncthreads();
    // G = L @ Ct  (256 rows, in smem; never hits global)
    #pragma unroll
    for (int ch = 0; ch < 8; ch++)
        gemm32<64,64,false>(L_s + ch*2048, Ct_s, nullptr, G_s + ch*32*65, 65);
    __syncthreads();
    // value head
    int i = tid >> 4, j = tid & 15;
    float wo_r[16];
    #pragma unroll
    for (int k = 0; k < 16; k++) wo_r[k] = wo_s[j*16 + k];
    float wjj = wo_r[j];
    float vout[8];
    #pragma unroll
    for (int o = 0; o < 8; o++) vout[o] = b2v[o];
    for (int t = 0; t < 64; t++) {
        float m = 0.f;
        #pragma unroll
        for (int k = 0; k < 16; k++) m = fmaf(wo_r[k], G_s[(i*16 + k)*65 + t], m);
        float gij = G_s[(i*16 + j)*65 + t];
        float fbt = fb_s[t];
        float h = U_s[j*65 + t] + 0.0625f * (m + fbt + wjj * (Fp_s[j*65 + t] - gij - fbt));
        float ht = leaky(h);
        #pragma unroll
        for (int o = 0; o < 8; o++) vout[o] = fmaf(fv2_s[o*64 + t], ht, vout[o]);
    }
    float4* dst = reinterpret_cast<float4*>(out_val + (size_t)(b*256 + tid)*8);
    dst[0] = make_float4(vout[0], vout[1], vout[2], vout[3]);
    dst[1] = make_float4(vout[4], vout[5], vout[6], vout[7]);
    // weights_obsz for this batch: out[b*4096 + o] = wo_s[o & 255]
    const float4* wo4 = reinterpret_cast<const float4*>(wo_s);
    #pragma unroll
    for (int k = 0; k < 4; k++) {
        int q = k*256 + tid;                    // [0,1024) float4s within b
        out4[b*1024 + q] = wo4[q & 63];
    }
}

// ---------------- launcher ----------------
extern "C" void kernel_launch(void* const* d_in, const int* in_sizes, int n_in,
                              void* d_out, int out_size)
{
    const float* obs  = (const float*)d_in[0];
    const float* pol  = (const float*)d_in[1];
    const float* act  = (const float*)d_in[2];
    const float* kw1  = (const float*)d_in[3];  const float* kw1b = (const float*)d_in[4];
    const float* kw2  = (const float*)d_in[5];  const float* kw2b = (const float*)d_in[6];
    const float* qw1  = (const float*)d_in[7];  const float* qw1b = (const float*)d_in[8];
    const float* qw2  = (const float*)d_in[9];  const float* qw2b = (const float*)d_in[10];
    const float* ko1  = (const float*)d_in[11]; const float* ko1b = (const float*)d_in[12];
    const float* ko2  = (const float*)d_in[13]; const float* ko2b = (const float*)d_in[14];
    const float* qo1  = (const float*)d_in[15]; const float* qo1b = (const float*)d_in[16];
    const float* qo2  = (const float*)d_in[17]; const float* qo2b = (const float*)d_in[18];
    const float* av1  = (const float*)d_in[19]; const float* av1b = (const float*)d_in[20];
    const float* av2  = (const float*)d_in[21]; const float* av2b = (const float*)d_in[22];
    const float* fv1  = (const float*)d_in[23]; const float* fv1b = (const float*)d_in[24];
    const float* fv2  = (const float*)d_in[25]; const float* fv2b = (const float*)d_in[26];

    float* out      = (float*)d_out;
    float* out_val  = out;
    float* out_wz   = out + 262144;
    float* out_obsz = out + 294912;

    const int SM1 = 24480 * 4;   // 97920
    const int SM2 = 42408 * 4;   // 169632

    cudaFuncSetAttribute(L1, cudaFuncAttributeMaxDynamicSharedMemorySize, SM1);
    cudaFuncSetAttribute(L2, cudaFuncAttributeMaxDynamicSharedMemorySize, SM2);

    L1<<<129, NTHREADS, SM1>>>(obs, pol, act,
                               kw1, kw1b, kw2, kw2b, qw1, qw1b, qw2, qw2b,
                               ko1, ko1b, ko2, ko2b, qo1, qo1b, qo2, qo2b,
                               av1, av1b, av2, av2b, fv1, fv1b, out_wz);
    L2<<<128, NTHREADS, SM2>>>(fv2, fv2b, out_val,
                               reinterpret_cast<float4*>(out_obsz));
}